// round 12
// baseline (speedup 1.0000x reference)
#include <cuda_runtime.h>
#include <cuda_bf16.h>
#include <math.h>
#include <stdint.h>

// Problem constants
#define S_   100
#define U_   128
#define H_   256
#define V_   10000
#define H3_  768
#define MTOT (S_ * U_)        // 12800
#define KFC  512
#define KA   256              // K of the main fc GEMM (out_w part only)

// Scratch (device globals; no dynamic allocation allowed)
__device__ float g_GI[MTOT * H3_];          // (S*U, 3H) input-side gates
__device__ float g_out[MTOT * H_];          // (S, U, H) GRU outputs
__device__ __nv_bfloat16 g_Ahi[(size_t)MTOT * KA];  // out_w hi bf16
__device__ __nv_bfloat16 g_Alo[(size_t)MTOT * KA];  // out_w lo bf16
__device__ __nv_bfloat16 g_Bhi[(size_t)V_ * KA];    // fc_W[:, :256] hi bf16
__device__ __nv_bfloat16 g_Blo[(size_t)V_ * KA];    // fc_W[:, :256] lo bf16
__device__ float g_C[(size_t)U_ * V_];              // p_u @ fc_W[:,256:]^T + fc_b

// ---------------------------------------------------------------------------
// Helpers
// ---------------------------------------------------------------------------
__device__ __forceinline__ void fma2(unsigned long long& d,
                                     unsigned long long a,
                                     unsigned long long b)
{
    asm("fma.rn.f32x2 %0, %1, %2, %0;" : "+l"(d) : "l"(a), "l"(b));
}

__device__ __forceinline__ float hsum2(unsigned long long v)
{
    float lo, hi;
    asm("mov.b64 {%0,%1}, %2;" : "=f"(lo), "=f"(hi) : "l"(v));
    return lo + hi;
}

__device__ __forceinline__ void split_bf16(float v, __nv_bfloat16& h, __nv_bfloat16& l)
{
    h = __float2bfloat16_rn(v);
    l = __float2bfloat16_rn(v - __bfloat162float(h));
}

__device__ __forceinline__ uint32_t smem_u32(const void* p)
{
    return (uint32_t)__cvta_generic_to_shared(p);
}

__device__ __forceinline__ void ldsm_x4(uint32_t addr, uint32_t* r)
{
    asm volatile("ldmatrix.sync.aligned.m8n8.x4.shared.b16 {%0,%1,%2,%3}, [%4];"
                 : "=r"(r[0]), "=r"(r[1]), "=r"(r[2]), "=r"(r[3]) : "r"(addr));
}

__device__ __forceinline__ void mma_bf16(float* d, const uint32_t* a, uint32_t b0, uint32_t b1)
{
    asm volatile(
        "mma.sync.aligned.m16n8k16.row.col.f32.bf16.bf16.f32 "
        "{%0,%1,%2,%3},{%4,%5,%6,%7},{%8,%9},{%0,%1,%2,%3};"
        : "+f"(d[0]), "+f"(d[1]), "+f"(d[2]), "+f"(d[3])
        : "r"(a[0]), "r"(a[1]), "r"(a[2]), "r"(a[3]), "r"(b0), "r"(b1));
}

__device__ __forceinline__ void cp16(uint32_t dst, const void* src, int srcsz)
{
    asm volatile("cp.async.cg.shared.global [%0], [%1], 16, %2;"
                 :: "r"(dst), "l"(src), "r"(srcsz) : "memory");
}
#define CP_COMMIT() asm volatile("cp.async.commit_group;" ::: "memory")
#define CP_WAIT0()  asm volatile("cp.async.wait_group 0;" ::: "memory")

// ---------------------------------------------------------------------------
// Kernel 0: split fc_W[:, :256] into bf16 hi/lo  (fc_W row-major (V, 512))
// ---------------------------------------------------------------------------
__global__ __launch_bounds__(256) void k_splitB(const float* __restrict__ W)
{
    const size_t i = ((size_t)blockIdx.x * 256 + threadIdx.x) * 8;
    if (i >= (size_t)V_ * KA) return;
    const size_t row = i >> 8;          // / 256
    const size_t col = i & 255;
    const float* src = W + row * KFC + col;
    float4 v0 = *(const float4*)(src);
    float4 v1 = *(const float4*)(src + 4);
    __align__(16) __nv_bfloat16 h[8], l[8];
    split_bf16(v0.x, h[0], l[0]); split_bf16(v0.y, h[1], l[1]);
    split_bf16(v0.z, h[2], l[2]); split_bf16(v0.w, h[3], l[3]);
    split_bf16(v1.x, h[4], l[4]); split_bf16(v1.y, h[5], l[5]);
    split_bf16(v1.z, h[6], l[6]); split_bf16(v1.w, h[7], l[7]);
    *(uint4*)(g_Bhi + i) = *(uint4*)h;
    *(uint4*)(g_Blo + i) = *(uint4*)l;
}

// ---------------------------------------------------------------------------
// Kernel 1: GI = gather(enc_W, x) @ W_ih^T + b_ih  (fp32 SIMT)
// ---------------------------------------------------------------------------
__global__ __launch_bounds__(256) void k_gi(
    const int* __restrict__ x,
    const float* __restrict__ enc_W,
    const float* __restrict__ W_ih,
    const float* __restrict__ b_ih)
{
    __shared__ float As[16][68];
    __shared__ float Bs[16][68];
    __shared__ int rowIdx[64];

    const int tid = threadIdx.x;
    const int mBase = blockIdx.x * 64;
    const int nBase = blockIdx.y * 64;

    if (tid < 64) rowIdx[tid] = x[mBase + tid];
    __syncthreads();

    const int tr = tid / 16;
    const int tc = tid % 16;
    const int lr = tid / 4;
    const int lq = tid % 4;

    float acc[4][4];
#pragma unroll
    for (int r = 0; r < 4; ++r)
#pragma unroll
        for (int c = 0; c < 4; ++c) acc[r][c] = 0.f;

    const int arow = rowIdx[lr];

    for (int k0 = 0; k0 < H_; k0 += 16) {
        float4 av = *(const float4*)(enc_W + (size_t)arow * H_ + k0 + lq * 4);
        float4 bv = *(const float4*)(W_ih + (size_t)(nBase + lr) * H_ + k0 + lq * 4);
        __syncthreads();
        As[lq * 4 + 0][lr] = av.x; As[lq * 4 + 1][lr] = av.y;
        As[lq * 4 + 2][lr] = av.z; As[lq * 4 + 3][lr] = av.w;
        Bs[lq * 4 + 0][lr] = bv.x; Bs[lq * 4 + 1][lr] = bv.y;
        Bs[lq * 4 + 2][lr] = bv.z; Bs[lq * 4 + 3][lr] = bv.w;
        __syncthreads();
#pragma unroll
        for (int k = 0; k < 16; ++k) {
            float a[4], b[4];
#pragma unroll
            for (int r = 0; r < 4; ++r) a[r] = As[k][tr * 4 + r];
#pragma unroll
            for (int c = 0; c < 4; ++c) b[c] = Bs[k][tc * 4 + c];
#pragma unroll
            for (int r = 0; r < 4; ++r)
#pragma unroll
                for (int c = 0; c < 4; ++c) acc[r][c] += a[r] * b[c];
        }
    }

#pragma unroll
    for (int r = 0; r < 4; ++r) {
        const int m = mBase + tr * 4 + r;
        float* row = g_GI + (size_t)m * H3_;
#pragma unroll
        for (int c = 0; c < 4; ++c) {
            const int n = nBase + tc * 4 + c;
            row[n] = acc[r][c] + b_ih[n];
        }
    }
}

// ---------------------------------------------------------------------------
// Kernel 1b: g_C[u][n] = p_u[u] @ fc_W[n, 256:512] + fc_b[n]   (fp32, exact)
// M=128, N=10000, K=256.  64x64 tile.
// ---------------------------------------------------------------------------
__global__ __launch_bounds__(256) void k_fc_pu(
    const int* __restrict__ active_user,
    const float* __restrict__ user_W,
    const float* __restrict__ fc_W,
    const float* __restrict__ fc_b)
{
    __shared__ float As[16][68];
    __shared__ float Bs[16][68];
    __shared__ int rowIdx[64];

    const int tid = threadIdx.x;
    const int mBase = blockIdx.x * 64;
    const int nBase = blockIdx.y * 64;

    if (tid < 64) rowIdx[tid] = active_user[mBase + tid];
    __syncthreads();

    const int tr = tid / 16;
    const int tc = tid % 16;
    const int lr = tid / 4;
    const int lq = tid % 4;

    float acc[4][4];
#pragma unroll
    for (int r = 0; r < 4; ++r)
#pragma unroll
        for (int c = 0; c < 4; ++c) acc[r][c] = 0.f;

    const int arow = rowIdx[lr];
    const int nB = nBase + lr;
    const float4 z4 = make_float4(0.f, 0.f, 0.f, 0.f);

    for (int k0 = 0; k0 < H_; k0 += 16) {
        float4 av = *(const float4*)(user_W + (size_t)arow * H_ + k0 + lq * 4);
        float4 bv = (nB < V_)
            ? *(const float4*)(fc_W + (size_t)nB * KFC + 256 + k0 + lq * 4) : z4;
        __syncthreads();
        As[lq * 4 + 0][lr] = av.x; As[lq * 4 + 1][lr] = av.y;
        As[lq * 4 + 2][lr] = av.z; As[lq * 4 + 3][lr] = av.w;
        Bs[lq * 4 + 0][lr] = bv.x; Bs[lq * 4 + 1][lr] = bv.y;
        Bs[lq * 4 + 2][lr] = bv.z; Bs[lq * 4 + 3][lr] = bv.w;
        __syncthreads();
#pragma unroll
        for (int k = 0; k < 16; ++k) {
            float a[4], b[4];
#pragma unroll
            for (int r = 0; r < 4; ++r) a[r] = As[k][tr * 4 + r];
#pragma unroll
            for (int c = 0; c < 4; ++c) b[c] = Bs[k][tc * 4 + c];
#pragma unroll
            for (int r = 0; r < 4; ++r)
#pragma unroll
                for (int c = 0; c < 4; ++c) acc[r][c] += a[r] * b[c];
        }
    }

#pragma unroll
    for (int r = 0; r < 4; ++r) {
        const int m = mBase + tr * 4 + r;
#pragma unroll
        for (int c = 0; c < 4; ++c) {
            const int n = nBase + tc * 4 + c;
            if (n < V_) g_C[(size_t)m * V_ + n] = acc[r][c] + fc_b[n];
        }
    }
}

// ---------------------------------------------------------------------------
// Kernel 2: GRU scan (packed f32x2 FMA phase-1)
// ---------------------------------------------------------------------------
__global__ __launch_bounds__(256) void k_gru(
    const float* __restrict__ h0,
    const float* __restrict__ W_hh,
    const float* __restrict__ b_hh)
{
    const int u0 = blockIdx.x * 4;
    const int tid = threadIdx.x;

    __shared__ float hs[4][H_];
    __shared__ float ghs[4][H3_];

    for (int i = tid; i < 4 * H_; i += 256) {
        const int u = i / H_, k = i % H_;
        hs[u][k] = h0[(size_t)(u0 + u) * H_ + k];
    }
    __syncthreads();

    const ulonglong2* W0 = (const ulonglong2*)(W_hh + (size_t)(tid)       * H_);
    const ulonglong2* W1 = (const ulonglong2*)(W_hh + (size_t)(tid + 256) * H_);
    const ulonglong2* W2 = (const ulonglong2*)(W_hh + (size_t)(tid + 512) * H_);
    const float bh0 = b_hh[tid], bh1 = b_hh[tid + 256], bh2 = b_hh[tid + 512];

    const int uu = tid >> 6;
    const int kk = (tid & 63) * 4;

    for (int t = 0; t < S_; ++t) {
        unsigned long long a0[4] = {0ull, 0ull, 0ull, 0ull};
        unsigned long long a1[4] = {0ull, 0ull, 0ull, 0ull};
        unsigned long long a2[4] = {0ull, 0ull, 0ull, 0ull};

#pragma unroll 4
        for (int k4 = 0; k4 < H_ / 4; ++k4) {
            ulonglong2 w0 = W0[k4], w1 = W1[k4], w2 = W2[k4];
#pragma unroll
            for (int u = 0; u < 4; ++u) {
                ulonglong2 h4 = *(const ulonglong2*)&hs[u][k4 * 4];
                fma2(a0[u], w0.x, h4.x); fma2(a0[u], w0.y, h4.y);
                fma2(a1[u], w1.x, h4.x); fma2(a1[u], w1.y, h4.y);
                fma2(a2[u], w2.x, h4.x); fma2(a2[u], w2.y, h4.y);
            }
        }
#pragma unroll
        for (int u = 0; u < 4; ++u) {
            ghs[u][tid]       = hsum2(a0[u]) + bh0;
            ghs[u][tid + 256] = hsum2(a1[u]) + bh1;
            ghs[u][tid + 512] = hsum2(a2[u]) + bh2;
        }
        __syncthreads();

        const float* GIrow = g_GI + ((size_t)t * U_ + (u0 + uu)) * H3_;
        float4 ir = *(const float4*)(GIrow + kk);
        float4 iz = *(const float4*)(GIrow + H_ + kk);
        float4 in4 = *(const float4*)(GIrow + 2 * H_ + kk);
        float4 hr = *(const float4*)&ghs[uu][kk];
        float4 hz = *(const float4*)&ghs[uu][H_ + kk];
        float4 hn = *(const float4*)&ghs[uu][2 * H_ + kk];
        float4 hp = *(const float4*)&hs[uu][kk];

        float4 hnew;
        {
            float r = 1.f / (1.f + expf(-(ir.x + hr.x)));
            float z = 1.f / (1.f + expf(-(iz.x + hz.x)));
            float n = tanhf(in4.x + r * hn.x);
            hnew.x = (1.f - z) * n + z * hp.x;
        }
        {
            float r = 1.f / (1.f + expf(-(ir.y + hr.y)));
            float z = 1.f / (1.f + expf(-(iz.y + hz.y)));
            float n = tanhf(in4.y + r * hn.y);
            hnew.y = (1.f - z) * n + z * hp.y;
        }
        {
            float r = 1.f / (1.f + expf(-(ir.z + hr.z)));
            float z = 1.f / (1.f + expf(-(iz.z + hz.z)));
            float n = tanhf(in4.z + r * hn.z);
            hnew.z = (1.f - z) * n + z * hp.z;
        }
        {
            float r = 1.f / (1.f + expf(-(ir.w + hr.w)));
            float z = 1.f / (1.f + expf(-(iz.w + hz.w)));
            float n = tanhf(in4.w + r * hn.w);
            hnew.w = (1.f - z) * n + z * hp.w;
        }

        *(float4*)&hs[uu][kk] = hnew;
        *(float4*)(g_out + ((size_t)t * U_ + (u0 + uu)) * H_ + kk) = hnew;
        __syncthreads();
    }
}

// ---------------------------------------------------------------------------
// Kernel 3: causal ST weights + weighted sum -> out_w hi/lo bf16
// ---------------------------------------------------------------------------
__global__ __launch_bounds__(128) void k_outw(
    const float* __restrict__ t_in,
    const float* __restrict__ s_in)
{
    const int i = blockIdx.x;
    const int u = blockIdx.y;
    const int tid = threadIdx.x;

    __shared__ float w[S_];

    const float ti = t_in[i * U_ + u];
    const float si0 = s_in[(i * U_ + u) * 2 + 0];
    const float si1 = s_in[(i * U_ + u) * 2 + 1];

    if (tid <= i && tid < S_) {
        const int j = tid;
        const float dt = ti - t_in[j * U_ + u];
        const float dx = si0 - s_in[(j * U_ + u) * 2 + 0];
        const float dy = si1 - s_in[(j * U_ + u) * 2 + 1];
        const float dist = sqrtf(dx * dx + dy * dy);
        const float a = (cosf(dt * (6.2831853071795864f / 86400.f)) + 1.f) * 0.5f
                        * expf(dt * (-0.1f / 86400.f));
        const float b = expf(-dist * 100.f);
        w[j] = a * b + 1e-10f;
    }
    __syncthreads();

    float sum = 0.f;
    for (int j = 0; j <= i; ++j) sum += w[j];
    const float inv = 1.f / sum;

    float acc0 = 0.f, acc1 = 0.f;
    for (int j = 0; j <= i; ++j) {
        const float wj = w[j];
        const float* orow = g_out + ((size_t)j * U_ + u) * H_;
        acc0 += wj * orow[tid];
        acc1 += wj * orow[tid + 128];
    }

    const size_t m = (size_t)i * U_ + u;
    __nv_bfloat16 h, l;
    split_bf16(acc0 * inv, h, l);
    g_Ahi[m * KA + tid] = h;
    g_Alo[m * KA + tid] = l;
    split_bf16(acc1 * inv, h, l);
    g_Ahi[m * KA + tid + 128] = h;
    g_Alo[m * KA + tid + 128] = l;
}

// ---------------------------------------------------------------------------
// Kernel 4: y = out_w @ fc_W[:, :256]^T + g_C  (3-pass bf16 mma.sync)
// M=12800, N=10000, K=256. Block 128x128, BK=64, cp.async double buffer.
// 8 warps x (64x32) warp tile. FLD=72 padding -> conflict-free ldmatrix.
// Rows of an M-tile are exactly users 0..127 (m = i*128+u), so the g_C
// broadcast-add indexes by in-block row.
// ---------------------------------------------------------------------------
#define FLD2 72
#define ARR_B (128 * FLD2 * 2)     // 18432 bytes per array
#define STG_B (4 * ARR_B)          // 73728 bytes per stage
#define FC_DYN (2 * STG_B)         // 147456

__global__ __launch_bounds__(256, 1) void k_fc(float* __restrict__ out)
{
    extern __shared__ char dynsm[];

    const int tid = threadIdx.x;
    const int lane = tid & 31;
    const int wid = tid >> 5;
    const int g = lane >> 2;
    const int c = lane & 3;
    const int mw = (wid >> 2) * 64;
    const int nw = (wid & 3) * 32;
    const int mBase = blockIdx.x * 128;
    const int nBase = blockIdx.y * 128;

    float acc[4][4][4];
#pragma unroll
    for (int mt = 0; mt < 4; ++mt)
#pragma unroll
        for (int nt = 0; nt < 4; ++nt)
#pragma unroll
            for (int i = 0; i < 4; ++i) acc[mt][nt][i] = 0.f;

    // ldmatrix per-warp relative offsets (within a stage's array)
    const int lrow = lane & 15;
    const int lcol = (lane >> 4) * 8;
    uint32_t offA[4], offB[2];
#pragma unroll
    for (int mt = 0; mt < 4; ++mt)
        offA[mt] = (uint32_t)(((mw + mt * 16 + lrow) * FLD2 + lcol) * 2);
#pragma unroll
    for (int np = 0; np < 2; ++np)
        offB[np] = (uint32_t)(((nw + np * 16 + lrow) * FLD2 + lcol) * 2);

    const uint32_t sm0 = smem_u32(dynsm);

    // cp.async loader: 4 arrays x 128 rows x 8 x 16B = 4096 ops / 256 thr = 16
    auto issue = [&](int s, int st) {
        const uint32_t stg = sm0 + st * STG_B;
        const int kofs = s * 64;
#pragma unroll
        for (int r = 0; r < 16; ++r) {
            const int idx = tid + r * 256;
            const int arr = idx >> 10;
            const int row = (idx >> 3) & 127;
            const int q = idx & 7;
            const uint32_t dst = stg + arr * ARR_B + (row * FLD2 + q * 8) * 2;
            const __nv_bfloat16* src;
            int sz = 16;
            if (arr == 0)
                src = g_Ahi + (size_t)(mBase + row) * KA + kofs + q * 8;
            else if (arr == 1)
                src = g_Alo + (size_t)(mBase + row) * KA + kofs + q * 8;
            else {
                const __nv_bfloat16* base = (arr == 2) ? g_Bhi : g_Blo;
                const int n = nBase + row;
                if (n < V_) {
                    src = base + (size_t)n * KA + kofs + q * 8;
                } else {
                    src = base;   // valid address; sz=0 -> full zero-fill
                    sz = 0;
                }
            }
            cp16(dst, src, sz);
        }
    };

    issue(0, 0);
    CP_COMMIT();
    CP_WAIT0();
    __syncthreads();

    const int NSTG = KA / 64;   // 4
    for (int s = 0; s < NSTG; ++s) {
        const int st = s & 1;
        if (s + 1 < NSTG) { issue(s + 1, st ^ 1); CP_COMMIT(); }

        const uint32_t stg = sm0 + st * STG_B;
        const uint32_t sAh = stg;
        const uint32_t sAl = stg + ARR_B;
        const uint32_t sBh = stg + 2 * ARR_B;
        const uint32_t sBl = stg + 3 * ARR_B;

#pragma unroll
        for (int j = 0; j < 4; ++j) {
            const uint32_t jb = j * 32;   // 16 bf16 = 32 bytes
            uint32_t ah[4][4], al[4][4], bh[2][4], bl[2][4];
#pragma unroll
            for (int mt = 0; mt < 4; ++mt) {
                ldsm_x4(sAh + offA[mt] + jb, ah[mt]);
                ldsm_x4(sAl + offA[mt] + jb, al[mt]);
            }
#pragma unroll
            for (int np = 0; np < 2; ++np) {
                ldsm_x4(sBh + offB[np] + jb, bh[np]);
                ldsm_x4(sBl + offB[np] + jb, bl[np]);
            }
            // pass 1: hi*hi
#pragma unroll
            for (int mt = 0; mt < 4; ++mt)
#pragma unroll
                for (int nt = 0; nt < 4; ++nt)
                    mma_bf16(acc[mt][nt], ah[mt], bh[nt >> 1][nt & 1], bh[nt >> 1][2 + (nt & 1)]);
            // pass 2: hi*lo
#pragma unroll
            for (int mt = 0; mt < 4; ++mt)
#pragma unroll
                for (int nt = 0; nt < 4; ++nt)
                    mma_bf16(acc[mt][nt], ah[mt], bl[nt >> 1][nt & 1], bl[nt >> 1][2 + (nt & 1)]);
            // pass 3: lo*hi
#pragma unroll
            for (int mt = 0; mt < 4; ++mt)
#pragma unroll
                for (int nt = 0; nt < 4; ++nt)
                    mma_bf16(acc[mt][nt], al[mt], bh[nt >> 1][nt & 1], bh[nt >> 1][2 + (nt & 1)]);
        }

        if (s + 1 < NSTG) {
            CP_WAIT0();
            __syncthreads();
        }
    }

    // epilogue: add g_C[row-in-block][n] (pu-term + bias), store fp32
#pragma unroll
    for (int mt = 0; mt < 4; ++mt) {
        const int mr = mw + mt * 16 + g;           // in-block row = user id
        const int m0 = mBase + mr;
#pragma unroll
        for (int nt = 0; nt < 4; ++nt) {
            const int n0 = nBase + nw + nt * 8 + c * 2;
            if (n0 < V_) {
                const float2 c0 = *(const float2*)(g_C + (size_t)mr * V_ + n0);
                const float2 c1 = *(const float2*)(g_C + (size_t)(mr + 8) * V_ + n0);
                float* p0 = out + (size_t)m0 * V_ + n0;
                p0[0] = acc[mt][nt][0] + c0.x;
                p0[1] = acc[mt][nt][1] + c0.y;
                float* p1 = out + (size_t)(m0 + 8) * V_ + n0;
                p1[0] = acc[mt][nt][2] + c1.x;
                p1[1] = acc[mt][nt][3] + c1.y;
            }
        }
    }
}

// ---------------------------------------------------------------------------
// Kernel 5: h_last -> tail of output
// ---------------------------------------------------------------------------
__global__ void k_hlast(float* __restrict__ out)
{
    const int idx = blockIdx.x * blockDim.x + threadIdx.x;
    if (idx < U_ * H_)
        out[(size_t)S_ * U_ * V_ + idx] = g_out[(size_t)(S_ - 1) * U_ * H_ + idx];
}

// ---------------------------------------------------------------------------
// Launch
// ---------------------------------------------------------------------------
extern "C" void kernel_launch(void* const* d_in, const int* in_sizes, int n_in,
                              void* d_out, int out_size)
{
    (void)in_sizes; (void)n_in; (void)out_size;
    const int*   x      = (const int*)  d_in[0];
    const float* t_in   = (const float*)d_in[1];
    const float* s_in   = (const float*)d_in[2];
    const float* h0     = (const float*)d_in[5];
    const int*   au     = (const int*)  d_in[6];
    const float* enc_W  = (const float*)d_in[7];
    const float* user_W = (const float*)d_in[8];
    const float* W_ih   = (const float*)d_in[9];
    const float* W_hh   = (const float*)d_in[10];
    const float* b_ih   = (const float*)d_in[11];
    const float* b_hh   = (const float*)d_in[12];
    const float* fc_W   = (const float*)d_in[13];
    const float* fc_b   = (const float*)d_in[14];
    float* out = (float*)d_out;

    cudaFuncSetAttribute(k_fc, cudaFuncAttributeMaxDynamicSharedMemorySize, FC_DYN);

    k_splitB<<<(V_ * KA / 8 + 255) / 256, 256>>>(fc_W);
    k_fc_pu<<<dim3(2, (V_ + 63) / 64), 256>>>(au, user_W, fc_W, fc_b);
    k_gi<<<dim3(MTOT / 64, H3_ / 64), 256>>>(x, enc_W, W_ih, b_ih);
    k_gru<<<U_ / 4, 256>>>(h0, W_hh, b_hh);
    k_hlast<<<(U_ * H_ + 255) / 256, 256>>>(out);
    k_outw<<<dim3(S_, U_), 128>>>(t_in, s_in);
    k_fc<<<dim3(MTOT / 128, (V_ + 127) / 128), 256, FC_DYN>>>(out);
}

// round 15
// speedup vs baseline: 1.5822x; 1.5822x over previous
#include <cuda_runtime.h>
#include <cuda_bf16.h>
#include <math.h>
#include <stdint.h>

// Problem constants
#define S_   100
#define U_   128
#define H_   256
#define V_   10000
#define H3_  768
#define MTOT (S_ * U_)        // 12800
#define KFC  512
#define KA   256              // K of the main fc GEMM (out_w part only)

// Scratch (device globals; no dynamic allocation allowed)
__device__ float g_GI[MTOT * H3_];          // (S*U, 3H) input-side gates
__device__ float g_out[MTOT * H_];          // (S, U, H) GRU outputs
__device__ __nv_bfloat16 g_Ahi[(size_t)MTOT * KA];  // out_w hi bf16
__device__ __nv_bfloat16 g_Alo[(size_t)MTOT * KA];  // out_w lo bf16
__device__ __nv_bfloat16 g_Bhi[(size_t)V_ * KA];    // fc_W[:, :256] hi bf16
__device__ __nv_bfloat16 g_Blo[(size_t)V_ * KA];    // fc_W[:, :256] lo bf16
__device__ float g_C[(size_t)U_ * V_];              // p_u @ fc_W[:,256:]^T + fc_b

// ---------------------------------------------------------------------------
// Helpers
// ---------------------------------------------------------------------------
__device__ __forceinline__ void fma2(unsigned long long& d,
                                     unsigned long long a,
                                     unsigned long long b)
{
    asm("fma.rn.f32x2 %0, %1, %2, %0;" : "+l"(d) : "l"(a), "l"(b));
}

__device__ __forceinline__ float hsum2(unsigned long long v)
{
    float lo, hi;
    asm("mov.b64 {%0,%1}, %2;" : "=f"(lo), "=f"(hi) : "l"(v));
    return lo + hi;
}

__device__ __forceinline__ void split_bf16(float v, __nv_bfloat16& h, __nv_bfloat16& l)
{
    h = __float2bfloat16_rn(v);
    l = __float2bfloat16_rn(v - __bfloat162float(h));
}

__device__ __forceinline__ void ldsm_x4(uint32_t addr, uint32_t* r)
{
    asm volatile("ldmatrix.sync.aligned.m8n8.x4.shared.b16 {%0,%1,%2,%3}, [%4];"
                 : "=r"(r[0]), "=r"(r[1]), "=r"(r[2]), "=r"(r[3]) : "r"(addr));
}

__device__ __forceinline__ void mma_bf16(float* d, const uint32_t* a, uint32_t b0, uint32_t b1)
{
    asm volatile(
        "mma.sync.aligned.m16n8k16.row.col.f32.bf16.bf16.f32 "
        "{%0,%1,%2,%3},{%4,%5,%6,%7},{%8,%9},{%0,%1,%2,%3};"
        : "+f"(d[0]), "+f"(d[1]), "+f"(d[2]), "+f"(d[3])
        : "r"(a[0]), "r"(a[1]), "r"(a[2]), "r"(a[3]), "r"(b0), "r"(b1));
}

// ---------------------------------------------------------------------------
// Kernel 0: split fc_W[:, :256] into bf16 hi/lo  (fc_W row-major (V, 512))
// ---------------------------------------------------------------------------
__global__ __launch_bounds__(256) void k_splitB(const float* __restrict__ W)
{
    const size_t i = ((size_t)blockIdx.x * 256 + threadIdx.x) * 8;
    if (i >= (size_t)V_ * KA) return;
    const size_t row = i >> 8;          // / 256
    const size_t col = i & 255;
    const float* src = W + row * KFC + col;
    float4 v0 = *(const float4*)(src);
    float4 v1 = *(const float4*)(src + 4);
    __align__(16) __nv_bfloat16 h[8], l[8];
    split_bf16(v0.x, h[0], l[0]); split_bf16(v0.y, h[1], l[1]);
    split_bf16(v0.z, h[2], l[2]); split_bf16(v0.w, h[3], l[3]);
    split_bf16(v1.x, h[4], l[4]); split_bf16(v1.y, h[5], l[5]);
    split_bf16(v1.z, h[6], l[6]); split_bf16(v1.w, h[7], l[7]);
    *(uint4*)(g_Bhi + i) = *(uint4*)h;
    *(uint4*)(g_Blo + i) = *(uint4*)l;
}

// ---------------------------------------------------------------------------
// Kernel 1: GI = gather(enc_W, x) @ W_ih^T + b_ih  (fp32 SIMT)
// ---------------------------------------------------------------------------
__global__ __launch_bounds__(256) void k_gi(
    const int* __restrict__ x,
    const float* __restrict__ enc_W,
    const float* __restrict__ W_ih,
    const float* __restrict__ b_ih)
{
    __shared__ float As[16][68];
    __shared__ float Bs[16][68];
    __shared__ int rowIdx[64];

    const int tid = threadIdx.x;
    const int mBase = blockIdx.x * 64;
    const int nBase = blockIdx.y * 64;

    if (tid < 64) rowIdx[tid] = x[mBase + tid];
    __syncthreads();

    const int tr = tid / 16;
    const int tc = tid % 16;
    const int lr = tid / 4;
    const int lq = tid % 4;

    float acc[4][4];
#pragma unroll
    for (int r = 0; r < 4; ++r)
#pragma unroll
        for (int c = 0; c < 4; ++c) acc[r][c] = 0.f;

    const int arow = rowIdx[lr];

    for (int k0 = 0; k0 < H_; k0 += 16) {
        float4 av = *(const float4*)(enc_W + (size_t)arow * H_ + k0 + lq * 4);
        float4 bv = *(const float4*)(W_ih + (size_t)(nBase + lr) * H_ + k0 + lq * 4);
        __syncthreads();
        As[lq * 4 + 0][lr] = av.x; As[lq * 4 + 1][lr] = av.y;
        As[lq * 4 + 2][lr] = av.z; As[lq * 4 + 3][lr] = av.w;
        Bs[lq * 4 + 0][lr] = bv.x; Bs[lq * 4 + 1][lr] = bv.y;
        Bs[lq * 4 + 2][lr] = bv.z; Bs[lq * 4 + 3][lr] = bv.w;
        __syncthreads();
#pragma unroll
        for (int k = 0; k < 16; ++k) {
            float a[4], b[4];
#pragma unroll
            for (int r = 0; r < 4; ++r) a[r] = As[k][tr * 4 + r];
#pragma unroll
            for (int c = 0; c < 4; ++c) b[c] = Bs[k][tc * 4 + c];
#pragma unroll
            for (int r = 0; r < 4; ++r)
#pragma unroll
                for (int c = 0; c < 4; ++c) acc[r][c] += a[r] * b[c];
        }
    }

#pragma unroll
    for (int r = 0; r < 4; ++r) {
        const int m = mBase + tr * 4 + r;
        float* row = g_GI + (size_t)m * H3_;
#pragma unroll
        for (int c = 0; c < 4; ++c) {
            const int n = nBase + tc * 4 + c;
            row[n] = acc[r][c] + b_ih[n];
        }
    }
}

// ---------------------------------------------------------------------------
// Kernel 1b: g_C[u][n] = p_u[u] @ fc_W[n, 256:512] + fc_b[n]   (fp32, exact)
// ---------------------------------------------------------------------------
__global__ __launch_bounds__(256) void k_fc_pu(
    const int* __restrict__ active_user,
    const float* __restrict__ user_W,
    const float* __restrict__ fc_W,
    const float* __restrict__ fc_b)
{
    __shared__ float As[16][68];
    __shared__ float Bs[16][68];
    __shared__ int rowIdx[64];

    const int tid = threadIdx.x;
    const int mBase = blockIdx.x * 64;
    const int nBase = blockIdx.y * 64;

    if (tid < 64) rowIdx[tid] = active_user[mBase + tid];
    __syncthreads();

    const int tr = tid / 16;
    const int tc = tid % 16;
    const int lr = tid / 4;
    const int lq = tid % 4;

    float acc[4][4];
#pragma unroll
    for (int r = 0; r < 4; ++r)
#pragma unroll
        for (int c = 0; c < 4; ++c) acc[r][c] = 0.f;

    const int arow = rowIdx[lr];
    const int nB = nBase + lr;
    const float4 z4 = make_float4(0.f, 0.f, 0.f, 0.f);

    for (int k0 = 0; k0 < H_; k0 += 16) {
        float4 av = *(const float4*)(user_W + (size_t)arow * H_ + k0 + lq * 4);
        float4 bv = (nB < V_)
            ? *(const float4*)(fc_W + (size_t)nB * KFC + 256 + k0 + lq * 4) : z4;
        __syncthreads();
        As[lq * 4 + 0][lr] = av.x; As[lq * 4 + 1][lr] = av.y;
        As[lq * 4 + 2][lr] = av.z; As[lq * 4 + 3][lr] = av.w;
        Bs[lq * 4 + 0][lr] = bv.x; Bs[lq * 4 + 1][lr] = bv.y;
        Bs[lq * 4 + 2][lr] = bv.z; Bs[lq * 4 + 3][lr] = bv.w;
        __syncthreads();
#pragma unroll
        for (int k = 0; k < 16; ++k) {
            float a[4], b[4];
#pragma unroll
            for (int r = 0; r < 4; ++r) a[r] = As[k][tr * 4 + r];
#pragma unroll
            for (int c = 0; c < 4; ++c) b[c] = Bs[k][tc * 4 + c];
#pragma unroll
            for (int r = 0; r < 4; ++r)
#pragma unroll
                for (int c = 0; c < 4; ++c) acc[r][c] += a[r] * b[c];
        }
    }

#pragma unroll
    for (int r = 0; r < 4; ++r) {
        const int m = mBase + tr * 4 + r;
#pragma unroll
        for (int c = 0; c < 4; ++c) {
            const int n = nBase + tc * 4 + c;
            if (n < V_) g_C[(size_t)m * V_ + n] = acc[r][c] + fc_b[n];
        }
    }
}

// ---------------------------------------------------------------------------
// Kernel 2: GRU scan (packed f32x2 FMA phase-1)
// ---------------------------------------------------------------------------
__global__ __launch_bounds__(256) void k_gru(
    const float* __restrict__ h0,
    const float* __restrict__ W_hh,
    const float* __restrict__ b_hh)
{
    const int u0 = blockIdx.x * 4;
    const int tid = threadIdx.x;

    __shared__ float hs[4][H_];
    __shared__ float ghs[4][H3_];

    for (int i = tid; i < 4 * H_; i += 256) {
        const int u = i / H_, k = i % H_;
        hs[u][k] = h0[(size_t)(u0 + u) * H_ + k];
    }
    __syncthreads();

    const ulonglong2* W0 = (const ulonglong2*)(W_hh + (size_t)(tid)       * H_);
    const ulonglong2* W1 = (const ulonglong2*)(W_hh + (size_t)(tid + 256) * H_);
    const ulonglong2* W2 = (const ulonglong2*)(W_hh + (size_t)(tid + 512) * H_);
    const float bh0 = b_hh[tid], bh1 = b_hh[tid + 256], bh2 = b_hh[tid + 512];

    const int uu = tid >> 6;
    const int kk = (tid & 63) * 4;

    for (int t = 0; t < S_; ++t) {
        unsigned long long a0[4] = {0ull, 0ull, 0ull, 0ull};
        unsigned long long a1[4] = {0ull, 0ull, 0ull, 0ull};
        unsigned long long a2[4] = {0ull, 0ull, 0ull, 0ull};

#pragma unroll 4
        for (int k4 = 0; k4 < H_ / 4; ++k4) {
            ulonglong2 w0 = W0[k4], w1 = W1[k4], w2 = W2[k4];
#pragma unroll
            for (int u = 0; u < 4; ++u) {
                ulonglong2 h4 = *(const ulonglong2*)&hs[u][k4 * 4];
                fma2(a0[u], w0.x, h4.x); fma2(a0[u], w0.y, h4.y);
                fma2(a1[u], w1.x, h4.x); fma2(a1[u], w1.y, h4.y);
                fma2(a2[u], w2.x, h4.x); fma2(a2[u], w2.y, h4.y);
            }
        }
#pragma unroll
        for (int u = 0; u < 4; ++u) {
            ghs[u][tid]       = hsum2(a0[u]) + bh0;
            ghs[u][tid + 256] = hsum2(a1[u]) + bh1;
            ghs[u][tid + 512] = hsum2(a2[u]) + bh2;
        }
        __syncthreads();

        const float* GIrow = g_GI + ((size_t)t * U_ + (u0 + uu)) * H3_;
        float4 ir = *(const float4*)(GIrow + kk);
        float4 iz = *(const float4*)(GIrow + H_ + kk);
        float4 in4 = *(const float4*)(GIrow + 2 * H_ + kk);
        float4 hr = *(const float4*)&ghs[uu][kk];
        float4 hz = *(const float4*)&ghs[uu][H_ + kk];
        float4 hn = *(const float4*)&ghs[uu][2 * H_ + kk];
        float4 hp = *(const float4*)&hs[uu][kk];

        float4 hnew;
        {
            float r = 1.f / (1.f + expf(-(ir.x + hr.x)));
            float z = 1.f / (1.f + expf(-(iz.x + hz.x)));
            float n = tanhf(in4.x + r * hn.x);
            hnew.x = (1.f - z) * n + z * hp.x;
        }
        {
            float r = 1.f / (1.f + expf(-(ir.y + hr.y)));
            float z = 1.f / (1.f + expf(-(iz.y + hz.y)));
            float n = tanhf(in4.y + r * hn.y);
            hnew.y = (1.f - z) * n + z * hp.y;
        }
        {
            float r = 1.f / (1.f + expf(-(ir.z + hr.z)));
            float z = 1.f / (1.f + expf(-(iz.z + hz.z)));
            float n = tanhf(in4.z + r * hn.z);
            hnew.z = (1.f - z) * n + z * hp.z;
        }
        {
            float r = 1.f / (1.f + expf(-(ir.w + hr.w)));
            float z = 1.f / (1.f + expf(-(iz.w + hz.w)));
            float n = tanhf(in4.w + r * hn.w);
            hnew.w = (1.f - z) * n + z * hp.w;
        }

        *(float4*)&hs[uu][kk] = hnew;
        *(float4*)(g_out + ((size_t)t * U_ + (u0 + uu)) * H_ + kk) = hnew;
        __syncthreads();
    }
}

// ---------------------------------------------------------------------------
// Kernel 3: causal ST weights + weighted sum -> out_w hi/lo bf16
// ---------------------------------------------------------------------------
__global__ __launch_bounds__(128) void k_outw(
    const float* __restrict__ t_in,
    const float* __restrict__ s_in)
{
    const int i = blockIdx.x;
    const int u = blockIdx.y;
    const int tid = threadIdx.x;

    __shared__ float w[S_];

    const float ti = t_in[i * U_ + u];
    const float si0 = s_in[(i * U_ + u) * 2 + 0];
    const float si1 = s_in[(i * U_ + u) * 2 + 1];

    if (tid <= i && tid < S_) {
        const int j = tid;
        const float dt = ti - t_in[j * U_ + u];
        const float dx = si0 - s_in[(j * U_ + u) * 2 + 0];
        const float dy = si1 - s_in[(j * U_ + u) * 2 + 1];
        const float dist = sqrtf(dx * dx + dy * dy);
        const float a = (cosf(dt * (6.2831853071795864f / 86400.f)) + 1.f) * 0.5f
                        * expf(dt * (-0.1f / 86400.f));
        const float b = expf(-dist * 100.f);
        w[j] = a * b + 1e-10f;
    }
    __syncthreads();

    float sum = 0.f;
    for (int j = 0; j <= i; ++j) sum += w[j];
    const float inv = 1.f / sum;

    float acc0 = 0.f, acc1 = 0.f;
    for (int j = 0; j <= i; ++j) {
        const float wj = w[j];
        const float* orow = g_out + ((size_t)j * U_ + u) * H_;
        acc0 += wj * orow[tid];
        acc1 += wj * orow[tid + 128];
    }

    const size_t m = (size_t)i * U_ + u;
    __nv_bfloat16 h, l;
    split_bf16(acc0 * inv, h, l);
    g_Ahi[m * KA + tid] = h;
    g_Alo[m * KA + tid] = l;
    split_bf16(acc1 * inv, h, l);
    g_Ahi[m * KA + tid + 128] = h;
    g_Alo[m * KA + tid + 128] = l;
}

// ---------------------------------------------------------------------------
// Kernel 4: y = out_w @ fc_W[:, :256]^T + g_C  (3-pass bf16 mma.sync)
// EXACT structure of the R8-measured kernel (register-staged prefetch,
// FLD=40 padding), only K=512 -> 256 and the g_C epilogue differ.
// M=12800, N=10000, K=256. Block 128x128, BK=32, 8 warps x (64x32).
// ---------------------------------------------------------------------------
#define FLD 40   // bf16 elements per smem row (32 data + 8 pad)

__global__ __launch_bounds__(256, 1) void k_fc(float* __restrict__ out)
{
    __shared__ __nv_bfloat16 Ahs[128 * FLD];
    __shared__ __nv_bfloat16 Als[128 * FLD];
    __shared__ __nv_bfloat16 Bhs[128 * FLD];
    __shared__ __nv_bfloat16 Bls[128 * FLD];

    const int tid = threadIdx.x;
    const int lane = tid & 31;
    const int wid = tid >> 5;
    const int g = lane >> 2;
    const int c = lane & 3;
    const int mw = (wid >> 2) * 64;
    const int nw = (wid & 3) * 32;
    const int mBase = blockIdx.x * 128;
    const int nBase = blockIdx.y * 128;

    float acc[4][4][4];
#pragma unroll
    for (int mt = 0; mt < 4; ++mt)
#pragma unroll
        for (int nt = 0; nt < 4; ++nt)
#pragma unroll
            for (int i = 0; i < 4; ++i) acc[mt][nt][i] = 0.f;

    // ldmatrix address setup
    const int lrow = lane & 15;
    const int lcol = (lane >> 4) * 8;
    const uint32_t sAh = (uint32_t)__cvta_generic_to_shared(Ahs);
    const uint32_t sAl = (uint32_t)__cvta_generic_to_shared(Als);
    const uint32_t sBh = (uint32_t)__cvta_generic_to_shared(Bhs);
    const uint32_t sBl = (uint32_t)__cvta_generic_to_shared(Bls);
    uint32_t offA[4], offB[2];
#pragma unroll
    for (int mt = 0; mt < 4; ++mt)
        offA[mt] = (uint32_t)(((mw + mt * 16 + lrow) * FLD + lcol) * 2);
#pragma unroll
    for (int np = 0; np < 2; ++np)
        offB[np] = (uint32_t)(((nw + np * 16 + lrow) * FLD + lcol) * 2);

    const uint4 z4 = make_uint4(0u, 0u, 0u, 0u);

    // loader mapping: 512 uint4 per array (128 rows x 4 quads of 8 bf16)
    uint4 avh[2], avl[2], bvh[2], bvl[2];
#pragma unroll
    for (int r = 0; r < 2; ++r) {
        const int idx = tid + r * 256;
        const int row = idx >> 2;
        const int kq = (idx & 3) * 8;
        const size_t aoff = (size_t)(mBase + row) * KA + kq;
        avh[r] = *(const uint4*)(g_Ahi + aoff);
        avl[r] = *(const uint4*)(g_Alo + aoff);
        const int n = nBase + row;
        const size_t boff = (size_t)n * KA + kq;
        bvh[r] = (n < V_) ? *(const uint4*)(g_Bhi + boff) : z4;
        bvl[r] = (n < V_) ? *(const uint4*)(g_Blo + boff) : z4;
    }
#pragma unroll
    for (int r = 0; r < 2; ++r) {
        const int idx = tid + r * 256;
        const int row = idx >> 2;
        const int kq = (idx & 3) * 8;
        *(uint4*)(Ahs + row * FLD + kq) = avh[r];
        *(uint4*)(Als + row * FLD + kq) = avl[r];
        *(uint4*)(Bhs + row * FLD + kq) = bvh[r];
        *(uint4*)(Bls + row * FLD + kq) = bvl[r];
    }
    __syncthreads();

    for (int s = 0; s < KA / 32; ++s) {
        if (s < KA / 32 - 1) {
            const int k0 = (s + 1) * 32;
#pragma unroll
            for (int r = 0; r < 2; ++r) {
                const int idx = tid + r * 256;
                const int row = idx >> 2;
                const int kq = (idx & 3) * 8;
                const size_t aoff = (size_t)(mBase + row) * KA + k0 + kq;
                avh[r] = *(const uint4*)(g_Ahi + aoff);
                avl[r] = *(const uint4*)(g_Alo + aoff);
                const int n = nBase + row;
                const size_t boff = (size_t)n * KA + k0 + kq;
                bvh[r] = (n < V_) ? *(const uint4*)(g_Bhi + boff) : z4;
                bvl[r] = (n < V_) ? *(const uint4*)(g_Blo + boff) : z4;
            }
        }

#pragma unroll
        for (int j = 0; j < 2; ++j) {
            const uint32_t jb = j * 32;  // 16 bf16 = 32 bytes
            uint32_t ah[4][4], al[4][4], bh[2][4], bl[2][4];
#pragma unroll
            for (int mt = 0; mt < 4; ++mt) {
                ldsm_x4(sAh + offA[mt] + jb, ah[mt]);
                ldsm_x4(sAl + offA[mt] + jb, al[mt]);
            }
#pragma unroll
            for (int np = 0; np < 2; ++np) {
                ldsm_x4(sBh + offB[np] + jb, bh[np]);
                ldsm_x4(sBl + offB[np] + jb, bl[np]);
            }
            // pass 1: hi * hi
#pragma unroll
            for (int mt = 0; mt < 4; ++mt)
#pragma unroll
                for (int nt = 0; nt < 4; ++nt)
                    mma_bf16(acc[mt][nt], ah[mt], bh[nt >> 1][nt & 1], bh[nt >> 1][2 + (nt & 1)]);
            // pass 2: hi * lo
#pragma unroll
            for (int mt = 0; mt < 4; ++mt)
#pragma unroll
                for (int nt = 0; nt < 4; ++nt)
                    mma_bf16(acc[mt][nt], ah[mt], bl[nt >> 1][nt & 1], bl[nt >> 1][2 + (nt & 1)]);
            // pass 3: lo * hi
#pragma unroll
            for (int mt = 0; mt < 4; ++mt)
#pragma unroll
                for (int nt = 0; nt < 4; ++nt)
                    mma_bf16(acc[mt][nt], al[mt], bh[nt >> 1][nt & 1], bh[nt >> 1][2 + (nt & 1)]);
        }
        __syncthreads();
        if (s < KA / 32 - 1) {
#pragma unroll
            for (int r = 0; r < 2; ++r) {
                const int idx = tid + r * 256;
                const int row = idx >> 2;
                const int kq = (idx & 3) * 8;
                *(uint4*)(Ahs + row * FLD + kq) = avh[r];
                *(uint4*)(Als + row * FLD + kq) = avl[r];
                *(uint4*)(Bhs + row * FLD + kq) = bvh[r];
                *(uint4*)(Bls + row * FLD + kq) = bvl[r];
            }
            __syncthreads();
        }
    }

    // epilogue: add g_C[row-in-block][n] (pu-term + bias), store fp32
    // rows of the M-tile are users 0..127 (m = i*128 + u)
#pragma unroll
    for (int mt = 0; mt < 4; ++mt) {
        const int mr = mw + mt * 16 + g;           // in-block row = user id
        const int m0 = mBase + mr;
#pragma unroll
        for (int nt = 0; nt < 4; ++nt) {
            const int n0 = nBase + nw + nt * 8 + c * 2;
            if (n0 < V_) {
                const float2 c0 = *(const float2*)(g_C + (size_t)mr * V_ + n0);
                const float2 c1 = *(const float2*)(g_C + (size_t)(mr + 8) * V_ + n0);
                float* p0 = out + (size_t)m0 * V_ + n0;
                p0[0] = acc[mt][nt][0] + c0.x;
                p0[1] = acc[mt][nt][1] + c0.y;
                float* p1 = out + (size_t)(m0 + 8) * V_ + n0;
                p1[0] = acc[mt][nt][2] + c1.x;
                p1[1] = acc[mt][nt][3] + c1.y;
            }
        }
    }
}

// ---------------------------------------------------------------------------
// Kernel 5: h_last -> tail of output
// ---------------------------------------------------------------------------
__global__ void k_hlast(float* __restrict__ out)
{
    const int idx = blockIdx.x * blockDim.x + threadIdx.x;
    if (idx < U_ * H_)
        out[(size_t)S_ * U_ * V_ + idx] = g_out[(size_t)(S_ - 1) * U_ * H_ + idx];
}

// ---------------------------------------------------------------------------
// Launch
// ---------------------------------------------------------------------------
extern "C" void kernel_launch(void* const* d_in, const int* in_sizes, int n_in,
                              void* d_out, int out_size)
{
    (void)in_sizes; (void)n_in; (void)out_size;
    const int*   x      = (const int*)  d_in[0];
    const float* t_in   = (const float*)d_in[1];
    const float* s_in   = (const float*)d_in[2];
    const float* h0     = (const float*)d_in[5];
    const int*   au     = (const int*)  d_in[6];
    const float* enc_W  = (const float*)d_in[7];
    const float* user_W = (const float*)d_in[8];
    const float* W_ih   = (const float*)d_in[9];
    const float* W_hh   = (const float*)d_in[10];
    const float* b_ih   = (const float*)d_in[11];
    const float* b_hh   = (const float*)d_in[12];
    const float* fc_W   = (const float*)d_in[13];
    const float* fc_b   = (const float*)d_in[14];
    float* out = (float*)d_out;

    k_splitB<<<(V_ * KA / 8 + 255) / 256, 256>>>(fc_W);
    k_fc_pu<<<dim3(2, (V_ + 63) / 64), 256>>>(au, user_W, fc_W, fc_b);
    k_gi<<<dim3(MTOT / 64, H3_ / 64), 256>>>(x, enc_W, W_ih, b_ih);
    k_gru<<<U_ / 4, 256>>>(h0, W_hh, b_hh);
    k_hlast<<<(U_ * H_ + 255) / 256, 256>>>(out);
    k_outw<<<dim3(S_, U_), 128>>>(t_in, s_in);
    k_fc<<<dim3(MTOT / 128, (V_ + 127) / 128), 256>>>(out);
}

// round 16
// speedup vs baseline: 1.6711x; 1.0562x over previous
#include <cuda_runtime.h>
#include <cuda_bf16.h>
#include <math.h>
#include <stdint.h>

// Problem constants
#define S_   100
#define U_   128
#define H_   256
#define V_   10000
#define H3_  768
#define MTOT (S_ * U_)        // 12800
#define KFC  512
#define KA   256              // K of the main fc GEMM (out_w part only)

// Scratch (device globals; no dynamic allocation allowed)
__device__ float g_GI[MTOT * H3_];          // (S*U, 3H) input-side gates
__device__ float g_out[MTOT * H_];          // (S, U, H) GRU outputs
__device__ __nv_bfloat16 g_Ahi[(size_t)MTOT * KA];  // out_w hi bf16
__device__ __nv_bfloat16 g_Alo[(size_t)MTOT * KA];  // out_w lo bf16
__device__ __nv_bfloat16 g_Bhi[(size_t)V_ * KA];    // fc_W[:, :256] hi bf16
__device__ __nv_bfloat16 g_Blo[(size_t)V_ * KA];    // fc_W[:, :256] lo bf16
__device__ float g_C[(size_t)U_ * V_];              // p_u @ fc_W[:,256:]^T + fc_b

// ---------------------------------------------------------------------------
// Helpers
// ---------------------------------------------------------------------------
__device__ __forceinline__ void fma2(unsigned long long& d,
                                     unsigned long long a,
                                     unsigned long long b)
{
    asm("fma.rn.f32x2 %0, %1, %2, %0;" : "+l"(d) : "l"(a), "l"(b));
}

__device__ __forceinline__ float hsum2(unsigned long long v)
{
    float lo, hi;
    asm("mov.b64 {%0,%1}, %2;" : "=f"(lo), "=f"(hi) : "l"(v));
    return lo + hi;
}

__device__ __forceinline__ void split_bf16(float v, __nv_bfloat16& h, __nv_bfloat16& l)
{
    h = __float2bfloat16_rn(v);
    l = __float2bfloat16_rn(v - __bfloat162float(h));
}

__device__ __forceinline__ void ldsm_x4(uint32_t addr, uint32_t* r)
{
    asm volatile("ldmatrix.sync.aligned.m8n8.x4.shared.b16 {%0,%1,%2,%3}, [%4];"
                 : "=r"(r[0]), "=r"(r[1]), "=r"(r[2]), "=r"(r[3]) : "r"(addr));
}

__device__ __forceinline__ void mma_bf16(float* d, const uint32_t* a, uint32_t b0, uint32_t b1)
{
    asm volatile(
        "mma.sync.aligned.m16n8k16.row.col.f32.bf16.bf16.f32 "
        "{%0,%1,%2,%3},{%4,%5,%6,%7},{%8,%9},{%0,%1,%2,%3};"
        : "+f"(d[0]), "+f"(d[1]), "+f"(d[2]), "+f"(d[3])
        : "r"(a[0]), "r"(a[1]), "r"(a[2]), "r"(a[3]), "r"(b0), "r"(b1));
}

// ---------------------------------------------------------------------------
// Prep bodies (fused into one kernel so k_fc lands at launch index 3)
// ---------------------------------------------------------------------------
__device__ __forceinline__ void splitB_body(int b, const float* __restrict__ W)
{
    const size_t i = ((size_t)b * 256 + threadIdx.x) * 8;
    if (i >= (size_t)V_ * KA) return;
    const size_t row = i >> 8;
    const size_t col = i & 255;
    const float* src = W + row * KFC + col;
    float4 v0 = *(const float4*)(src);
    float4 v1 = *(const float4*)(src + 4);
    __align__(16) __nv_bfloat16 h[8], l[8];
    split_bf16(v0.x, h[0], l[0]); split_bf16(v0.y, h[1], l[1]);
    split_bf16(v0.z, h[2], l[2]); split_bf16(v0.w, h[3], l[3]);
    split_bf16(v1.x, h[4], l[4]); split_bf16(v1.y, h[5], l[5]);
    split_bf16(v1.z, h[6], l[6]); split_bf16(v1.w, h[7], l[7]);
    *(uint4*)(g_Bhi + i) = *(uint4*)h;
    *(uint4*)(g_Blo + i) = *(uint4*)l;
}

__device__ __forceinline__ void gi_body(
    int bx, int by,
    const int* __restrict__ x,
    const float* __restrict__ enc_W,
    const float* __restrict__ W_ih,
    const float* __restrict__ b_ih)
{
    __shared__ float As[16][68];
    __shared__ float Bs[16][68];
    __shared__ int rowIdx[64];

    const int tid = threadIdx.x;
    const int mBase = bx * 64;
    const int nBase = by * 64;

    if (tid < 64) rowIdx[tid] = x[mBase + tid];
    __syncthreads();

    const int tr = tid / 16;
    const int tc = tid % 16;
    const int lr = tid / 4;
    const int lq = tid % 4;

    float acc[4][4];
#pragma unroll
    for (int r = 0; r < 4; ++r)
#pragma unroll
        for (int c = 0; c < 4; ++c) acc[r][c] = 0.f;

    const int arow = rowIdx[lr];

    for (int k0 = 0; k0 < H_; k0 += 16) {
        float4 av = *(const float4*)(enc_W + (size_t)arow * H_ + k0 + lq * 4);
        float4 bv = *(const float4*)(W_ih + (size_t)(nBase + lr) * H_ + k0 + lq * 4);
        __syncthreads();
        As[lq * 4 + 0][lr] = av.x; As[lq * 4 + 1][lr] = av.y;
        As[lq * 4 + 2][lr] = av.z; As[lq * 4 + 3][lr] = av.w;
        Bs[lq * 4 + 0][lr] = bv.x; Bs[lq * 4 + 1][lr] = bv.y;
        Bs[lq * 4 + 2][lr] = bv.z; Bs[lq * 4 + 3][lr] = bv.w;
        __syncthreads();
#pragma unroll
        for (int k = 0; k < 16; ++k) {
            float a[4], b[4];
#pragma unroll
            for (int r = 0; r < 4; ++r) a[r] = As[k][tr * 4 + r];
#pragma unroll
            for (int c = 0; c < 4; ++c) b[c] = Bs[k][tc * 4 + c];
#pragma unroll
            for (int r = 0; r < 4; ++r)
#pragma unroll
                for (int c = 0; c < 4; ++c) acc[r][c] += a[r] * b[c];
        }
    }

#pragma unroll
    for (int r = 0; r < 4; ++r) {
        const int m = mBase + tr * 4 + r;
        float* row = g_GI + (size_t)m * H3_;
#pragma unroll
        for (int c = 0; c < 4; ++c) {
            const int n = nBase + tc * 4 + c;
            row[n] = acc[r][c] + b_ih[n];
        }
    }
}

__device__ __forceinline__ void fc_pu_body(
    int bx, int by,
    const int* __restrict__ active_user,
    const float* __restrict__ user_W,
    const float* __restrict__ fc_W,
    const float* __restrict__ fc_b)
{
    __shared__ float As2[16][68];
    __shared__ float Bs2[16][68];
    __shared__ int rowIdx2[64];

    const int tid = threadIdx.x;
    const int mBase = bx * 64;
    const int nBase = by * 64;

    if (tid < 64) rowIdx2[tid] = active_user[mBase + tid];
    __syncthreads();

    const int tr = tid / 16;
    const int tc = tid % 16;
    const int lr = tid / 4;
    const int lq = tid % 4;

    float acc[4][4];
#pragma unroll
    for (int r = 0; r < 4; ++r)
#pragma unroll
        for (int c = 0; c < 4; ++c) acc[r][c] = 0.f;

    const int arow = rowIdx2[lr];
    const int nB = nBase + lr;
    const float4 z4 = make_float4(0.f, 0.f, 0.f, 0.f);

    for (int k0 = 0; k0 < H_; k0 += 16) {
        float4 av = *(const float4*)(user_W + (size_t)arow * H_ + k0 + lq * 4);
        float4 bv = (nB < V_)
            ? *(const float4*)(fc_W + (size_t)nB * KFC + 256 + k0 + lq * 4) : z4;
        __syncthreads();
        As2[lq * 4 + 0][lr] = av.x; As2[lq * 4 + 1][lr] = av.y;
        As2[lq * 4 + 2][lr] = av.z; As2[lq * 4 + 3][lr] = av.w;
        Bs2[lq * 4 + 0][lr] = bv.x; Bs2[lq * 4 + 1][lr] = bv.y;
        Bs2[lq * 4 + 2][lr] = bv.z; Bs2[lq * 4 + 3][lr] = bv.w;
        __syncthreads();
#pragma unroll
        for (int k = 0; k < 16; ++k) {
            float a[4], b[4];
#pragma unroll
            for (int r = 0; r < 4; ++r) a[r] = As2[k][tr * 4 + r];
#pragma unroll
            for (int c = 0; c < 4; ++c) b[c] = Bs2[k][tc * 4 + c];
#pragma unroll
            for (int r = 0; r < 4; ++r)
#pragma unroll
                for (int c = 0; c < 4; ++c) acc[r][c] += a[r] * b[c];
        }
    }

#pragma unroll
    for (int r = 0; r < 4; ++r) {
        const int m = mBase + tr * 4 + r;
#pragma unroll
        for (int c = 0; c < 4; ++c) {
            const int n = nBase + tc * 4 + c;
            if (n < V_) g_C[(size_t)m * V_ + n] = acc[r][c] + fc_b[n];
        }
    }
}

// grid layout of the fused prep kernel
#define NB_GI_X 200
#define NB_GI_Y 12
#define NB_GI   (NB_GI_X * NB_GI_Y)         // 2400
#define NB_PU_X 2
#define NB_PU_Y 157
#define NB_PU   (NB_PU_X * NB_PU_Y)         // 314
#define NB_SB   ((V_ * KA / 8 + 255) / 256) // 1250
#define NB_PREP (NB_GI + NB_PU + NB_SB)

__global__ __launch_bounds__(256) void k_prep(
    const int* __restrict__ x,
    const float* __restrict__ enc_W,
    const float* __restrict__ W_ih,
    const float* __restrict__ b_ih,
    const int* __restrict__ active_user,
    const float* __restrict__ user_W,
    const float* __restrict__ fc_W,
    const float* __restrict__ fc_b)
{
    const int b = blockIdx.x;
    if (b < NB_GI) {
        gi_body(b % NB_GI_X, b / NB_GI_X, x, enc_W, W_ih, b_ih);
    } else if (b < NB_GI + NB_PU) {
        const int bb = b - NB_GI;
        fc_pu_body(bb % NB_PU_X, bb / NB_PU_X, active_user, user_W, fc_W, fc_b);
    } else {
        splitB_body(b - NB_GI - NB_PU, fc_W);
    }
}

// ---------------------------------------------------------------------------
// Kernel 2: GRU scan — 512 threads, K-split phase 1 (2x warps to hide the
// W_hh L2 stream), partials reduced through smem.
// ---------------------------------------------------------------------------
__global__ __launch_bounds__(512) void k_gru(
    const float* __restrict__ h0,
    const float* __restrict__ W_hh,
    const float* __restrict__ b_hh)
{
    const int u0 = blockIdx.x * 4;
    const int tid = threadIdx.x;

    __shared__ float hs[4][H_];         // 4 KB
    __shared__ float part[2][4][H3_];   // 24 KB
    __shared__ float ghs[4][H3_];       // 12 KB
    __shared__ float bsh[H3_];          // 3 KB

    for (int i = tid; i < 4 * H_; i += 512) {
        const int u = i / H_, k = i % H_;
        hs[u][k] = h0[(size_t)(u0 + u) * H_ + k];
    }
    for (int i = tid; i < H3_; i += 512) bsh[i] = b_hh[i];
    __syncthreads();

    const int half = tid >> 8;          // K-half 0/1
    const int r = tid & 255;            // gate row base (0..255)
    const int ko = half * (H_ / 2);     // 0 or 128

    const ulonglong2* W0 = (const ulonglong2*)(W_hh + (size_t)r * H_ + ko);
    const ulonglong2* W1 = (const ulonglong2*)(W_hh + (size_t)(r + 256) * H_ + ko);
    const ulonglong2* W2 = (const ulonglong2*)(W_hh + (size_t)(r + 512) * H_ + ko);

    const int uu = tid >> 7;            // phase-2 user 0..3
    const int kk = (tid & 127) * 2;     // phase-2 k pair

    for (int t = 0; t < S_; ++t) {
        unsigned long long a0[4] = {0ull, 0ull, 0ull, 0ull};
        unsigned long long a1[4] = {0ull, 0ull, 0ull, 0ull};
        unsigned long long a2[4] = {0ull, 0ull, 0ull, 0ull};

#pragma unroll 4
        for (int k4 = 0; k4 < H_ / 8; ++k4) {      // 32 iters over this K-half
            ulonglong2 w0 = W0[k4], w1 = W1[k4], w2 = W2[k4];
#pragma unroll
            for (int u = 0; u < 4; ++u) {
                ulonglong2 h4 = *(const ulonglong2*)&hs[u][ko + k4 * 4];
                fma2(a0[u], w0.x, h4.x); fma2(a0[u], w0.y, h4.y);
                fma2(a1[u], w1.x, h4.x); fma2(a1[u], w1.y, h4.y);
                fma2(a2[u], w2.x, h4.x); fma2(a2[u], w2.y, h4.y);
            }
        }
#pragma unroll
        for (int u = 0; u < 4; ++u) {
            part[half][u][r]       = hsum2(a0[u]);
            part[half][u][r + 256] = hsum2(a1[u]);
            part[half][u][r + 512] = hsum2(a2[u]);
        }
        __syncthreads();

        // reduce halves + bias: 4*768 = 3072 elems
        for (int i = tid; i < 4 * H3_; i += 512) {
            const int u = i / H3_, row = i % H3_;
            ghs[u][row] = part[0][u][row] + part[1][u][row] + bsh[row];
        }
        __syncthreads();

        // phase 2: gate nonlinearity + h update (2 floats per thread)
        const float* GIrow = g_GI + ((size_t)t * U_ + (u0 + uu)) * H3_;
        float2 ir = *(const float2*)(GIrow + kk);
        float2 iz = *(const float2*)(GIrow + H_ + kk);
        float2 in2 = *(const float2*)(GIrow + 2 * H_ + kk);
        float2 hr = *(const float2*)&ghs[uu][kk];
        float2 hz = *(const float2*)&ghs[uu][H_ + kk];
        float2 hn = *(const float2*)&ghs[uu][2 * H_ + kk];
        float2 hp = *(const float2*)&hs[uu][kk];

        float2 hnew;
        {
            float rr = 1.f / (1.f + expf(-(ir.x + hr.x)));
            float zz = 1.f / (1.f + expf(-(iz.x + hz.x)));
            float nn = tanhf(in2.x + rr * hn.x);
            hnew.x = (1.f - zz) * nn + zz * hp.x;
        }
        {
            float rr = 1.f / (1.f + expf(-(ir.y + hr.y)));
            float zz = 1.f / (1.f + expf(-(iz.y + hz.y)));
            float nn = tanhf(in2.y + rr * hn.y);
            hnew.y = (1.f - zz) * nn + zz * hp.y;
        }

        *(float2*)&hs[uu][kk] = hnew;
        *(float2*)(g_out + ((size_t)t * U_ + (u0 + uu)) * H_ + kk) = hnew;
        __syncthreads();
    }
}

// ---------------------------------------------------------------------------
// Kernel 3: causal ST weights + weighted sum -> out_w hi/lo bf16
// ---------------------------------------------------------------------------
__global__ __launch_bounds__(128) void k_outw(
    const float* __restrict__ t_in,
    const float* __restrict__ s_in)
{
    const int i = blockIdx.x;
    const int u = blockIdx.y;
    const int tid = threadIdx.x;

    __shared__ float w[S_];

    const float ti = t_in[i * U_ + u];
    const float si0 = s_in[(i * U_ + u) * 2 + 0];
    const float si1 = s_in[(i * U_ + u) * 2 + 1];

    if (tid <= i && tid < S_) {
        const int j = tid;
        const float dt = ti - t_in[j * U_ + u];
        const float dx = si0 - s_in[(j * U_ + u) * 2 + 0];
        const float dy = si1 - s_in[(j * U_ + u) * 2 + 1];
        const float dist = sqrtf(dx * dx + dy * dy);
        const float a = (cosf(dt * (6.2831853071795864f / 86400.f)) + 1.f) * 0.5f
                        * expf(dt * (-0.1f / 86400.f));
        const float b = expf(-dist * 100.f);
        w[j] = a * b + 1e-10f;
    }
    __syncthreads();

    float sum = 0.f;
    for (int j = 0; j <= i; ++j) sum += w[j];
    const float inv = 1.f / sum;

    float acc0 = 0.f, acc1 = 0.f;
    for (int j = 0; j <= i; ++j) {
        const float wj = w[j];
        const float* orow = g_out + ((size_t)j * U_ + u) * H_;
        acc0 += wj * orow[tid];
        acc1 += wj * orow[tid + 128];
    }

    const size_t m = (size_t)i * U_ + u;
    __nv_bfloat16 h, l;
    split_bf16(acc0 * inv, h, l);
    g_Ahi[m * KA + tid] = h;
    g_Alo[m * KA + tid] = l;
    split_bf16(acc1 * inv, h, l);
    g_Ahi[m * KA + tid + 128] = h;
    g_Alo[m * KA + tid + 128] = l;
}

// ---------------------------------------------------------------------------
// Kernel 4: y = out_w @ fc_W[:, :256]^T + g_C  (3-pass bf16 mma.sync)
// Same math/layout as the measured 3903us kernel; now 2 CTAs/SM
// (launch_bounds(256,2), no register prefetch -> inter-CTA overlap).
// ---------------------------------------------------------------------------
#define FLD 40   // bf16 elements per smem row (32 data + 8 pad)

__global__ __launch_bounds__(256, 2) void k_fc(float* __restrict__ out)
{
    __shared__ __nv_bfloat16 Ahs[128 * FLD];
    __shared__ __nv_bfloat16 Als[128 * FLD];
    __shared__ __nv_bfloat16 Bhs[128 * FLD];
    __shared__ __nv_bfloat16 Bls[128 * FLD];

    const int tid = threadIdx.x;
    const int lane = tid & 31;
    const int wid = tid >> 5;
    const int g = lane >> 2;
    const int c = lane & 3;
    const int mw = (wid >> 2) * 64;
    const int nw = (wid & 3) * 32;
    const int mBase = blockIdx.x * 128;
    const int nBase = blockIdx.y * 128;

    float acc[4][4][4];
#pragma unroll
    for (int mt = 0; mt < 4; ++mt)
#pragma unroll
        for (int nt = 0; nt < 4; ++nt)
#pragma unroll
            for (int i = 0; i < 4; ++i) acc[mt][nt][i] = 0.f;

    // ldmatrix address setup
    const int lrow = lane & 15;
    const int lcol = (lane >> 4) * 8;
    const uint32_t sAh = (uint32_t)__cvta_generic_to_shared(Ahs);
    const uint32_t sAl = (uint32_t)__cvta_generic_to_shared(Als);
    const uint32_t sBh = (uint32_t)__cvta_generic_to_shared(Bhs);
    const uint32_t sBl = (uint32_t)__cvta_generic_to_shared(Bls);
    uint32_t offA[4], offB[2];
#pragma unroll
    for (int mt = 0; mt < 4; ++mt)
        offA[mt] = (uint32_t)(((mw + mt * 16 + lrow) * FLD + lcol) * 2);
#pragma unroll
    for (int np = 0; np < 2; ++np)
        offB[np] = (uint32_t)(((nw + np * 16 + lrow) * FLD + lcol) * 2);

    const uint4 z4 = make_uint4(0u, 0u, 0u, 0u);

    for (int s = 0; s < KA / 32; ++s) {
        const int k0 = s * 32;
        if (s > 0) __syncthreads();    // previous stage fully consumed
        // load stage s directly gmem -> smem (other CTA's MMAs overlap this)
#pragma unroll
        for (int r = 0; r < 2; ++r) {
            const int idx = tid + r * 256;
            const int row = idx >> 2;
            const int kq = (idx & 3) * 8;
            const size_t aoff = (size_t)(mBase + row) * KA + k0 + kq;
            const uint4 avh = *(const uint4*)(g_Ahi + aoff);
            const uint4 avl = *(const uint4*)(g_Alo + aoff);
            const int n = nBase + row;
            const size_t boff = (size_t)n * KA + k0 + kq;
            const uint4 bvh = (n < V_) ? *(const uint4*)(g_Bhi + boff) : z4;
            const uint4 bvl = (n < V_) ? *(const uint4*)(g_Blo + boff) : z4;
            *(uint4*)(Ahs + row * FLD + kq) = avh;
            *(uint4*)(Als + row * FLD + kq) = avl;
            *(uint4*)(Bhs + row * FLD + kq) = bvh;
            *(uint4*)(Bls + row * FLD + kq) = bvl;
        }
        __syncthreads();

#pragma unroll
        for (int j = 0; j < 2; ++j) {
            const uint32_t jb = j * 32;  // 16 bf16 = 32 bytes
            uint32_t ah[4][4], al[4][4], bh[2][4], bl[2][4];
#pragma unroll
            for (int mt = 0; mt < 4; ++mt) {
                ldsm_x4(sAh + offA[mt] + jb, ah[mt]);
                ldsm_x4(sAl + offA[mt] + jb, al[mt]);
            }
#pragma unroll
            for (int np = 0; np < 2; ++np) {
                ldsm_x4(sBh + offB[np] + jb, bh[np]);
                ldsm_x4(sBl + offB[np] + jb, bl[np]);
            }
            // pass 1: hi * hi
#pragma unroll
            for (int mt = 0; mt < 4; ++mt)
#pragma unroll
                for (int nt = 0; nt < 4; ++nt)
                    mma_bf16(acc[mt][nt], ah[mt], bh[nt >> 1][nt & 1], bh[nt >> 1][2 + (nt & 1)]);
            // pass 2: hi * lo
#pragma unroll
            for (int mt = 0; mt < 4; ++mt)
#pragma unroll
                for (int nt = 0; nt < 4; ++nt)
                    mma_bf16(acc[mt][nt], ah[mt], bl[nt >> 1][nt & 1], bl[nt >> 1][2 + (nt & 1)]);
            // pass 3: lo * hi
#pragma unroll
            for (int mt = 0; mt < 4; ++mt)
#pragma unroll
                for (int nt = 0; nt < 4; ++nt)
                    mma_bf16(acc[mt][nt], al[mt], bh[nt >> 1][nt & 1], bh[nt >> 1][2 + (nt & 1)]);
        }
    }

    // epilogue: add g_C[row-in-block][n] (pu-term + bias), store fp32
    // rows of the M-tile are users 0..127 (m = i*128 + u)
#pragma unroll
    for (int mt = 0; mt < 4; ++mt) {
        const int mr = mw + mt * 16 + g;           // in-block row = user id
        const int m0 = mBase + mr;
#pragma unroll
        for (int nt = 0; nt < 4; ++nt) {
            const int n0 = nBase + nw + nt * 8 + c * 2;
            if (n0 < V_) {
                const float2 c0 = *(const float2*)(g_C + (size_t)mr * V_ + n0);
                const float2 c1 = *(const float2*)(g_C + (size_t)(mr + 8) * V_ + n0);
                float* p0 = out + (size_t)m0 * V_ + n0;
                p0[0] = acc[mt][nt][0] + c0.x;
                p0[1] = acc[mt][nt][1] + c0.y;
                float* p1 = out + (size_t)(m0 + 8) * V_ + n0;
                p1[0] = acc[mt][nt][2] + c1.x;
                p1[1] = acc[mt][nt][3] + c1.y;
            }
        }
    }
}

// ---------------------------------------------------------------------------
// Kernel 5: h_last -> tail of output
// ---------------------------------------------------------------------------
__global__ void k_hlast(float* __restrict__ out)
{
    const int idx = blockIdx.x * blockDim.x + threadIdx.x;
    if (idx < U_ * H_)
        out[(size_t)S_ * U_ * V_ + idx] = g_out[(size_t)(S_ - 1) * U_ * H_ + idx];
}

// ---------------------------------------------------------------------------
// Launch — order chosen so k_fc is launch index 3 (the one ncu captures)
// ---------------------------------------------------------------------------
extern "C" void kernel_launch(void* const* d_in, const int* in_sizes, int n_in,
                              void* d_out, int out_size)
{
    (void)in_sizes; (void)n_in; (void)out_size;
    const int*   x      = (const int*)  d_in[0];
    const float* t_in   = (const float*)d_in[1];
    const float* s_in   = (const float*)d_in[2];
    const float* h0     = (const float*)d_in[5];
    const int*   au     = (const int*)  d_in[6];
    const float* enc_W  = (const float*)d_in[7];
    const float* user_W = (const float*)d_in[8];
    const float* W_ih   = (const float*)d_in[9];
    const float* W_hh   = (const float*)d_in[10];
    const float* b_ih   = (const float*)d_in[11];
    const float* b_hh   = (const float*)d_in[12];
    const float* fc_W   = (const float*)d_in[13];
    const float* fc_b   = (const float*)d_in[14];
    float* out = (float*)d_out;

    k_prep<<<NB_PREP, 256>>>(x, enc_W, W_ih, b_ih, au, user_W, fc_W, fc_b);  // 0
    k_gru<<<U_ / 4, 512>>>(h0, W_hh, b_hh);                                  // 1
    k_outw<<<dim3(S_, U_), 128>>>(t_in, s_in);                               // 2
    k_fc<<<dim3(MTOT / 128, (V_ + 127) / 128), 256>>>(out);                  // 3  <- profiled
    k_hlast<<<(U_ * H_ + 255) / 256, 256>>>(out);                            // 4
}

// round 17
// speedup vs baseline: 2.1306x; 1.2750x over previous
#include <cuda_runtime.h>
#include <cuda_bf16.h>
#include <math.h>
#include <stdint.h>

// Problem constants
#define S_   100
#define U_   128
#define H_   256
#define V_   10000
#define H3_  768
#define MTOT (S_ * U_)        // 12800
#define KFC  512
#define KA   256              // K of the main fc GEMM (out_w part only)

// Scratch (device globals; no dynamic allocation allowed)
__device__ float g_GI[MTOT * H3_];          // (S*U, 3H) input-side gates
__device__ float g_out[MTOT * H_];          // (S, U, H) GRU outputs
__device__ float g_WT[H_ * H3_];            // W_hh transposed: [k][gate_row]
__device__ __nv_bfloat16 g_Ahi[(size_t)MTOT * KA];  // out_w hi bf16
__device__ __nv_bfloat16 g_Alo[(size_t)MTOT * KA];  // out_w lo bf16
__device__ __nv_bfloat16 g_Bhi[(size_t)V_ * KA];    // fc_W[:, :256] hi bf16
__device__ __nv_bfloat16 g_Blo[(size_t)V_ * KA];    // fc_W[:, :256] lo bf16
__device__ float g_C[(size_t)U_ * V_];              // p_u @ fc_W[:,256:]^T + fc_b

// ---------------------------------------------------------------------------
// Helpers
// ---------------------------------------------------------------------------
__device__ __forceinline__ void fma2(unsigned long long& d,
                                     unsigned long long a,
                                     unsigned long long b)
{
    asm("fma.rn.f32x2 %0, %1, %2, %0;" : "+l"(d) : "l"(a), "l"(b));
}

__device__ __forceinline__ void split_bf16(float v, __nv_bfloat16& h, __nv_bfloat16& l)
{
    h = __float2bfloat16_rn(v);
    l = __float2bfloat16_rn(v - __bfloat162float(h));
}

__device__ __forceinline__ void ldsm_x4(uint32_t addr, uint32_t* r)
{
    asm volatile("ldmatrix.sync.aligned.m8n8.x4.shared.b16 {%0,%1,%2,%3}, [%4];"
                 : "=r"(r[0]), "=r"(r[1]), "=r"(r[2]), "=r"(r[3]) : "r"(addr));
}

__device__ __forceinline__ void mma_bf16(float* d, const uint32_t* a, uint32_t b0, uint32_t b1)
{
    asm volatile(
        "mma.sync.aligned.m16n8k16.row.col.f32.bf16.bf16.f32 "
        "{%0,%1,%2,%3},{%4,%5,%6,%7},{%8,%9},{%0,%1,%2,%3};"
        : "+f"(d[0]), "+f"(d[1]), "+f"(d[2]), "+f"(d[3])
        : "r"(a[0]), "r"(a[1]), "r"(a[2]), "r"(a[3]), "r"(b0), "r"(b1));
}

// ---------------------------------------------------------------------------
// Prep bodies (fused into one kernel so k_fc lands at launch index 3)
// ---------------------------------------------------------------------------
__device__ __forceinline__ void splitB_body(int b, const float* __restrict__ W)
{
    const size_t i = ((size_t)b * 256 + threadIdx.x) * 8;
    if (i >= (size_t)V_ * KA) return;
    const size_t row = i >> 8;
    const size_t col = i & 255;
    const float* src = W + row * KFC + col;
    float4 v0 = *(const float4*)(src);
    float4 v1 = *(const float4*)(src + 4);
    __align__(16) __nv_bfloat16 h[8], l[8];
    split_bf16(v0.x, h[0], l[0]); split_bf16(v0.y, h[1], l[1]);
    split_bf16(v0.z, h[2], l[2]); split_bf16(v0.w, h[3], l[3]);
    split_bf16(v1.x, h[4], l[4]); split_bf16(v1.y, h[5], l[5]);
    split_bf16(v1.z, h[6], l[6]); split_bf16(v1.w, h[7], l[7]);
    *(uint4*)(g_Bhi + i) = *(uint4*)h;
    *(uint4*)(g_Blo + i) = *(uint4*)l;
}

__device__ __forceinline__ void tr_body(int b, const float* __restrict__ W_hh)
{
    __shared__ float tile[32][33];
    const int bx = b % (H_ / 32);          // k-tile   (8)
    const int by = b / (H_ / 32);          // row-tile (24)
    const int k0 = bx * 32, r0 = by * 32;
    const int tx = threadIdx.x & 31, ty0 = threadIdx.x >> 5;
#pragma unroll
    for (int j = 0; j < 4; ++j) {
        const int ty = ty0 + j * 8;
        tile[ty][tx] = W_hh[(size_t)(r0 + ty) * H_ + k0 + tx];
    }
    __syncthreads();
#pragma unroll
    for (int j = 0; j < 4; ++j) {
        const int ty = ty0 + j * 8;
        g_WT[(size_t)(k0 + ty) * H3_ + r0 + tx] = tile[tx][ty];
    }
}

__device__ __forceinline__ void gi_body(
    int bx, int by,
    const int* __restrict__ x,
    const float* __restrict__ enc_W,
    const float* __restrict__ W_ih,
    const float* __restrict__ b_ih)
{
    __shared__ float As[16][68];
    __shared__ float Bs[16][68];
    __shared__ int rowIdx[64];

    const int tid = threadIdx.x;
    const int mBase = bx * 64;
    const int nBase = by * 64;

    if (tid < 64) rowIdx[tid] = x[mBase + tid];
    __syncthreads();

    const int tr = tid / 16;
    const int tc = tid % 16;
    const int lr = tid / 4;
    const int lq = tid % 4;

    float acc[4][4];
#pragma unroll
    for (int r = 0; r < 4; ++r)
#pragma unroll
        for (int c = 0; c < 4; ++c) acc[r][c] = 0.f;

    const int arow = rowIdx[lr];

    for (int k0 = 0; k0 < H_; k0 += 16) {
        float4 av = *(const float4*)(enc_W + (size_t)arow * H_ + k0 + lq * 4);
        float4 bv = *(const float4*)(W_ih + (size_t)(nBase + lr) * H_ + k0 + lq * 4);
        __syncthreads();
        As[lq * 4 + 0][lr] = av.x; As[lq * 4 + 1][lr] = av.y;
        As[lq * 4 + 2][lr] = av.z; As[lq * 4 + 3][lr] = av.w;
        Bs[lq * 4 + 0][lr] = bv.x; Bs[lq * 4 + 1][lr] = bv.y;
        Bs[lq * 4 + 2][lr] = bv.z; Bs[lq * 4 + 3][lr] = bv.w;
        __syncthreads();
#pragma unroll
        for (int k = 0; k < 16; ++k) {
            float a[4], b[4];
#pragma unroll
            for (int r = 0; r < 4; ++r) a[r] = As[k][tr * 4 + r];
#pragma unroll
            for (int c = 0; c < 4; ++c) b[c] = Bs[k][tc * 4 + c];
#pragma unroll
            for (int r = 0; r < 4; ++r)
#pragma unroll
                for (int c = 0; c < 4; ++c) acc[r][c] += a[r] * b[c];
        }
    }

#pragma unroll
    for (int r = 0; r < 4; ++r) {
        const int m = mBase + tr * 4 + r;
        float* row = g_GI + (size_t)m * H3_;
#pragma unroll
        for (int c = 0; c < 4; ++c) {
            const int n = nBase + tc * 4 + c;
            row[n] = acc[r][c] + b_ih[n];
        }
    }
}

__device__ __forceinline__ void fc_pu_body(
    int bx, int by,
    const int* __restrict__ active_user,
    const float* __restrict__ user_W,
    const float* __restrict__ fc_W,
    const float* __restrict__ fc_b)
{
    __shared__ float As2[16][68];
    __shared__ float Bs2[16][68];
    __shared__ int rowIdx2[64];

    const int tid = threadIdx.x;
    const int mBase = bx * 64;
    const int nBase = by * 64;

    if (tid < 64) rowIdx2[tid] = active_user[mBase + tid];
    __syncthreads();

    const int tr = tid / 16;
    const int tc = tid % 16;
    const int lr = tid / 4;
    const int lq = tid % 4;

    float acc[4][4];
#pragma unroll
    for (int r = 0; r < 4; ++r)
#pragma unroll
        for (int c = 0; c < 4; ++c) acc[r][c] = 0.f;

    const int arow = rowIdx2[lr];
    const int nB = nBase + lr;
    const float4 z4 = make_float4(0.f, 0.f, 0.f, 0.f);

    for (int k0 = 0; k0 < H_; k0 += 16) {
        float4 av = *(const float4*)(user_W + (size_t)arow * H_ + k0 + lq * 4);
        float4 bv = (nB < V_)
            ? *(const float4*)(fc_W + (size_t)nB * KFC + 256 + k0 + lq * 4) : z4;
        __syncthreads();
        As2[lq * 4 + 0][lr] = av.x; As2[lq * 4 + 1][lr] = av.y;
        As2[lq * 4 + 2][lr] = av.z; As2[lq * 4 + 3][lr] = av.w;
        Bs2[lq * 4 + 0][lr] = bv.x; Bs2[lq * 4 + 1][lr] = bv.y;
        Bs2[lq * 4 + 2][lr] = bv.z; Bs2[lq * 4 + 3][lr] = bv.w;
        __syncthreads();
#pragma unroll
        for (int k = 0; k < 16; ++k) {
            float a[4], b[4];
#pragma unroll
            for (int r = 0; r < 4; ++r) a[r] = As2[k][tr * 4 + r];
#pragma unroll
            for (int c = 0; c < 4; ++c) b[c] = Bs2[k][tc * 4 + c];
#pragma unroll
            for (int r = 0; r < 4; ++r)
#pragma unroll
                for (int c = 0; c < 4; ++c) acc[r][c] += a[r] * b[c];
        }
    }

#pragma unroll
    for (int r = 0; r < 4; ++r) {
        const int m = mBase + tr * 4 + r;
#pragma unroll
        for (int c = 0; c < 4; ++c) {
            const int n = nBase + tc * 4 + c;
            if (n < V_) g_C[(size_t)m * V_ + n] = acc[r][c] + fc_b[n];
        }
    }
}

// grid layout of the fused prep kernel
#define NB_GI_X 200
#define NB_GI_Y 12
#define NB_GI   (NB_GI_X * NB_GI_Y)         // 2400
#define NB_PU_X 2
#define NB_PU_Y 157
#define NB_PU   (NB_PU_X * NB_PU_Y)         // 314
#define NB_SB   ((V_ * KA / 8 + 255) / 256) // 1250
#define NB_TR   ((H3_ / 32) * (H_ / 32))    // 192
#define NB_PREP (NB_GI + NB_PU + NB_SB + NB_TR)

__global__ __launch_bounds__(256) void k_prep(
    const int* __restrict__ x,
    const float* __restrict__ enc_W,
    const float* __restrict__ W_ih,
    const float* __restrict__ b_ih,
    const int* __restrict__ active_user,
    const float* __restrict__ user_W,
    const float* __restrict__ fc_W,
    const float* __restrict__ fc_b,
    const float* __restrict__ W_hh)
{
    const int b = blockIdx.x;
    if (b < NB_GI) {
        gi_body(b % NB_GI_X, b / NB_GI_X, x, enc_W, W_ih, b_ih);
    } else if (b < NB_GI + NB_PU) {
        const int bb = b - NB_GI;
        fc_pu_body(bb % NB_PU_X, bb / NB_PU_X, active_user, user_W, fc_W, fc_b);
    } else if (b < NB_GI + NB_PU + NB_SB) {
        splitB_body(b - NB_GI - NB_PU, fc_W);
    } else {
        tr_body(b - NB_GI - NB_PU - NB_SB, W_hh);
    }
}

// ---------------------------------------------------------------------------
// Kernel 2: GRU scan — coalesced k-major W_hh stream (g_WT), 384 threads.
// Thread t owns gate-row pair (2t, 2t+1); accumulates full K via fma.f32x2
// against an (h,h)-duplicated smem table -> no cross-thread reduction.
// ---------------------------------------------------------------------------
__global__ __launch_bounds__(384) void k_gru(
    const float* __restrict__ h0,
    const float* __restrict__ b_hh)
{
    const int u0 = blockIdx.x * 4;
    const int tid = threadIdx.x;

    __shared__ float hs[4][H_];                          // 4 KB
    __shared__ __align__(16) unsigned long long hdup[4][H_];  // 8 KB (h,h) pairs
    __shared__ float ghs[4][H3_];                        // 12 KB

    // init h + hdup
    for (int i = tid; i < 4 * H_; i += 384) {
        const int u = i >> 8, k = i & 255;
        const float h = h0[(size_t)(u0 + u) * H_ + k];
        hs[u][k] = h;
        unsigned long long p;
        asm("mov.b64 %0, {%1, %1};" : "=l"(p) : "f"(h));
        hdup[u][k] = p;
    }

    const int r2 = tid * 2;                                   // owned rows
    const float2 b2 = *(const float2*)(b_hh + r2);
    // g_WT[k][row] viewed as row-pairs: ull index = k*384 + tid
    const unsigned long long* WTp = (const unsigned long long*)g_WT;

    __syncthreads();

    for (int t = 0; t < S_; ++t) {
        // phase 1: gh[r2], gh[r2+1] = sum_k WT[k][r2..r2+1] * h[u][k]
        unsigned long long acc[4] = {0ull, 0ull, 0ull, 0ull};
#pragma unroll 4
        for (int k2 = 0; k2 < H_ / 2; ++k2) {
            const int k = k2 * 2;
            const unsigned long long w0 = WTp[(size_t)k * 384 + tid];
            const unsigned long long w1 = WTp[(size_t)(k + 1) * 384 + tid];
#pragma unroll
            for (int u = 0; u < 4; ++u) {
                const ulonglong2 hd = *(const ulonglong2*)&hdup[u][k];
                fma2(acc[u], w0, hd.x);
                fma2(acc[u], w1, hd.y);
            }
        }
#pragma unroll
        for (int u = 0; u < 4; ++u) {
            float lo, hi;
            asm("mov.b64 {%0,%1}, %2;" : "=f"(lo), "=f"(hi) : "l"(acc[u]));
            ghs[u][r2]     = lo + b2.x;
            ghs[u][r2 + 1] = hi + b2.y;
        }
        __syncthreads();

        // phase 2: gate nonlinearity + h update (1024 elems over 384 threads)
        for (int i = tid; i < 4 * H_; i += 384) {
            const int u = i >> 8, k = i & 255;
            const float* GIrow = g_GI + ((size_t)t * U_ + (u0 + u)) * H3_;
            const float ir = GIrow[k];
            const float iz = GIrow[H_ + k];
            const float in_ = GIrow[2 * H_ + k];
            const float hr = ghs[u][k];
            const float hz = ghs[u][H_ + k];
            const float hn = ghs[u][2 * H_ + k];
            const float hp = hs[u][k];

            const float rr = 1.f / (1.f + expf(-(ir + hr)));
            const float zz = 1.f / (1.f + expf(-(iz + hz)));
            const float nn = tanhf(in_ + rr * hn);
            const float hnew = (1.f - zz) * nn + zz * hp;

            hs[u][k] = hnew;
            unsigned long long p;
            asm("mov.b64 %0, {%1, %1};" : "=l"(p) : "f"(hnew));
            hdup[u][k] = p;
            g_out[((size_t)t * U_ + (u0 + u)) * H_ + k] = hnew;
        }
        __syncthreads();
    }
}

// ---------------------------------------------------------------------------
// Kernel 3: causal ST weights + weighted sum -> out_w hi/lo bf16
// ---------------------------------------------------------------------------
__global__ __launch_bounds__(128) void k_outw(
    const float* __restrict__ t_in,
    const float* __restrict__ s_in)
{
    const int i = blockIdx.x;
    const int u = blockIdx.y;
    const int tid = threadIdx.x;

    __shared__ float w[S_];

    const float ti = t_in[i * U_ + u];
    const float si0 = s_in[(i * U_ + u) * 2 + 0];
    const float si1 = s_in[(i * U_ + u) * 2 + 1];

    if (tid <= i && tid < S_) {
        const int j = tid;
        const float dt = ti - t_in[j * U_ + u];
        const float dx = si0 - s_in[(j * U_ + u) * 2 + 0];
        const float dy = si1 - s_in[(j * U_ + u) * 2 + 1];
        const float dist = sqrtf(dx * dx + dy * dy);
        const float a = (cosf(dt * (6.2831853071795864f / 86400.f)) + 1.f) * 0.5f
                        * expf(dt * (-0.1f / 86400.f));
        const float b = expf(-dist * 100.f);
        w[j] = a * b + 1e-10f;
    }
    __syncthreads();

    float sum = 0.f;
    for (int j = 0; j <= i; ++j) sum += w[j];
    const float inv = 1.f / sum;

    float acc0 = 0.f, acc1 = 0.f;
    for (int j = 0; j <= i; ++j) {
        const float wj = w[j];
        const float* orow = g_out + ((size_t)j * U_ + u) * H_;
        acc0 += wj * orow[tid];
        acc1 += wj * orow[tid + 128];
    }

    const size_t m = (size_t)i * U_ + u;
    __nv_bfloat16 h, l;
    split_bf16(acc0 * inv, h, l);
    g_Ahi[m * KA + tid] = h;
    g_Alo[m * KA + tid] = l;
    split_bf16(acc1 * inv, h, l);
    g_Ahi[m * KA + tid + 128] = h;
    g_Alo[m * KA + tid + 128] = l;
}

// ---------------------------------------------------------------------------
// Kernel 4: y = out_w @ fc_W[:, :256]^T + g_C  (3-pass bf16 mma.sync)
// Unchanged from the measured 726us version (2 CTAs/SM, inter-CTA overlap).
// ---------------------------------------------------------------------------
#define FLD 40   // bf16 elements per smem row (32 data + 8 pad)

__global__ __launch_bounds__(256, 2) void k_fc(float* __restrict__ out)
{
    __shared__ __nv_bfloat16 Ahs[128 * FLD];
    __shared__ __nv_bfloat16 Als[128 * FLD];
    __shared__ __nv_bfloat16 Bhs[128 * FLD];
    __shared__ __nv_bfloat16 Bls[128 * FLD];

    const int tid = threadIdx.x;
    const int lane = tid & 31;
    const int wid = tid >> 5;
    const int g = lane >> 2;
    const int c = lane & 3;
    const int mw = (wid >> 2) * 64;
    const int nw = (wid & 3) * 32;
    const int mBase = blockIdx.x * 128;
    const int nBase = blockIdx.y * 128;

    float acc[4][4][4];
#pragma unroll
    for (int mt = 0; mt < 4; ++mt)
#pragma unroll
        for (int nt = 0; nt < 4; ++nt)
#pragma unroll
            for (int i = 0; i < 4; ++i) acc[mt][nt][i] = 0.f;

    // ldmatrix address setup
    const int lrow = lane & 15;
    const int lcol = (lane >> 4) * 8;
    const uint32_t sAh = (uint32_t)__cvta_generic_to_shared(Ahs);
    const uint32_t sAl = (uint32_t)__cvta_generic_to_shared(Als);
    const uint32_t sBh = (uint32_t)__cvta_generic_to_shared(Bhs);
    const uint32_t sBl = (uint32_t)__cvta_generic_to_shared(Bls);
    uint32_t offA[4], offB[2];
#pragma unroll
    for (int mt = 0; mt < 4; ++mt)
        offA[mt] = (uint32_t)(((mw + mt * 16 + lrow) * FLD + lcol) * 2);
#pragma unroll
    for (int np = 0; np < 2; ++np)
        offB[np] = (uint32_t)(((nw + np * 16 + lrow) * FLD + lcol) * 2);

    const uint4 z4 = make_uint4(0u, 0u, 0u, 0u);

    for (int s = 0; s < KA / 32; ++s) {
        const int k0 = s * 32;
        if (s > 0) __syncthreads();    // previous stage fully consumed
        // load stage s directly gmem -> smem (other CTA's MMAs overlap this)
#pragma unroll
        for (int r = 0; r < 2; ++r) {
            const int idx = tid + r * 256;
            const int row = idx >> 2;
            const int kq = (idx & 3) * 8;
            const size_t aoff = (size_t)(mBase + row) * KA + k0 + kq;
            const uint4 avh = *(const uint4*)(g_Ahi + aoff);
            const uint4 avl = *(const uint4*)(g_Alo + aoff);
            const int n = nBase + row;
            const size_t boff = (size_t)n * KA + k0 + kq;
            const uint4 bvh = (n < V_) ? *(const uint4*)(g_Bhi + boff) : z4;
            const uint4 bvl = (n < V_) ? *(const uint4*)(g_Blo + boff) : z4;
            *(uint4*)(Ahs + row * FLD + kq) = avh;
            *(uint4*)(Als + row * FLD + kq) = avl;
            *(uint4*)(Bhs + row * FLD + kq) = bvh;
            *(uint4*)(Bls + row * FLD + kq) = bvl;
        }
        __syncthreads();

#pragma unroll
        for (int j = 0; j < 2; ++j) {
            const uint32_t jb = j * 32;  // 16 bf16 = 32 bytes
            uint32_t ah[4][4], al[4][4], bh[2][4], bl[2][4];
#pragma unroll
            for (int mt = 0; mt < 4; ++mt) {
                ldsm_x4(sAh + offA[mt] + jb, ah[mt]);
                ldsm_x4(sAl + offA[mt] + jb, al[mt]);
            }
#pragma unroll
            for (int np = 0; np < 2; ++np) {
                ldsm_x4(sBh + offB[np] + jb, bh[np]);
                ldsm_x4(sBl + offB[np] + jb, bl[np]);
            }
            // pass 1: hi * hi
#pragma unroll
            for (int mt = 0; mt < 4; ++mt)
#pragma unroll
                for (int nt = 0; nt < 4; ++nt)
                    mma_bf16(acc[mt][nt], ah[mt], bh[nt >> 1][nt & 1], bh[nt >> 1][2 + (nt & 1)]);
            // pass 2: hi * lo
#pragma unroll
            for (int mt = 0; mt < 4; ++mt)
#pragma unroll
                for (int nt = 0; nt < 4; ++nt)
                    mma_bf16(acc[mt][nt], ah[mt], bl[nt >> 1][nt & 1], bl[nt >> 1][2 + (nt & 1)]);
            // pass 3: lo * hi
#pragma unroll
            for (int mt = 0; mt < 4; ++mt)
#pragma unroll
                for (int nt = 0; nt < 4; ++nt)
                    mma_bf16(acc[mt][nt], al[mt], bh[nt >> 1][nt & 1], bh[nt >> 1][2 + (nt & 1)]);
        }
    }

    // epilogue: add g_C[row-in-block][n] (pu-term + bias), store fp32
#pragma unroll
    for (int mt = 0; mt < 4; ++mt) {
        const int mr = mw + mt * 16 + g;           // in-block row = user id
        const int m0 = mBase + mr;
#pragma unroll
        for (int nt = 0; nt < 4; ++nt) {
            const int n0 = nBase + nw + nt * 8 + c * 2;
            if (n0 < V_) {
                const float2 c0 = *(const float2*)(g_C + (size_t)mr * V_ + n0);
                const float2 c1 = *(const float2*)(g_C + (size_t)(mr + 8) * V_ + n0);
                float* p0 = out + (size_t)m0 * V_ + n0;
                p0[0] = acc[mt][nt][0] + c0.x;
                p0[1] = acc[mt][nt][1] + c0.y;
                float* p1 = out + (size_t)(m0 + 8) * V_ + n0;
                p1[0] = acc[mt][nt][2] + c1.x;
                p1[1] = acc[mt][nt][3] + c1.y;
            }
        }
    }
}

// ---------------------------------------------------------------------------
// Kernel 5: h_last -> tail of output
// ---------------------------------------------------------------------------
__global__ void k_hlast(float* __restrict__ out)
{
    const int idx = blockIdx.x * blockDim.x + threadIdx.x;
    if (idx < U_ * H_)
        out[(size_t)S_ * U_ * V_ + idx] = g_out[(size_t)(S_ - 1) * U_ * H_ + idx];
}

// ---------------------------------------------------------------------------
// Launch — k_fc stays at launch index 3 (the one ncu captures)
// ---------------------------------------------------------------------------
extern "C" void kernel_launch(void* const* d_in, const int* in_sizes, int n_in,
                              void* d_out, int out_size)
{
    (void)in_sizes; (void)n_in; (void)out_size;
    const int*   x      = (const int*)  d_in[0];
    const float* t_in   = (const float*)d_in[1];
    const float* s_in   = (const float*)d_in[2];
    const float* h0     = (const float*)d_in[5];
    const int*   au     = (const int*)  d_in[6];
    const float* enc_W  = (const float*)d_in[7];
    const float* user_W = (const float*)d_in[8];
    const float* W_ih   = (const float*)d_in[9];
    const float* W_hh   = (const float*)d_in[10];
    const float* b_ih   = (const float*)d_in[11];
    const float* b_hh   = (const float*)d_in[12];
    const float* fc_W   = (const float*)d_in[13];
    const float* fc_b   = (const float*)d_in[14];
    float* out = (float*)d_out;

    k_prep<<<NB_PREP, 256>>>(x, enc_W, W_ih, b_ih, au, user_W, fc_W, fc_b, W_hh); // 0
    k_gru<<<U_ / 4, 384>>>(h0, b_hh);                                             // 1
    k_outw<<<dim3(S_, U_), 128>>>(t_in, s_in);                                    // 2
    k_fc<<<dim3(MTOT / 128, (V_ + 127) / 128), 256>>>(out);                       // 3  <- profiled
    k_hlast<<<(U_ * H_ + 255) / 256, 256>>>(out);                                 // 4
}